// round 1
// baseline (speedup 1.0000x reference)
#include <cuda_runtime.h>
#include <cuda_bf16.h>
#include <math.h>

// Problem constants
constexpr int NNODES = 40000;
constexpr int NEDGES = 640000;
constexpr int D = 128;        // feature dim (in & hidden)
constexpr int DH = 64;        // hidden//2
constexpr int NCLS = 10;

// ---------------------------------------------------------------------------
// Scratch (static device globals — no allocation at runtime)
// ---------------------------------------------------------------------------
__device__ int   g_cnt_in[NNODES];
__device__ int   g_cnt_out[NNODES];
__device__ float g_norm_in[NNODES];
__device__ float g_norm_out[NNODES];
__device__ int   g_row_ptr[NNODES + 1];
__device__ int   g_cursor[NNODES];
__device__ int   g_esrc[NEDGES];          // src node of each edge, sorted by dst (CSR)
__device__ float g_agg[(size_t)NNODES * D];
__device__ float g_h1 [(size_t)NNODES * D];
__device__ float g_h2 [(size_t)NNODES * D];
__device__ float g_t  [(size_t)NNODES * DH];

// ---------------------------------------------------------------------------
// 1. zero degree counters
// ---------------------------------------------------------------------------
__global__ void zero_counts_kernel() {
    int i = blockIdx.x * blockDim.x + threadIdx.x;
    if (i < NNODES) { g_cnt_in[i] = 0; g_cnt_out[i] = 0; }
}

// 2. degree histogram (also the CSR count for dst)
__global__ void histogram_kernel(const int* __restrict__ src, const int* __restrict__ dst) {
    int e = blockIdx.x * blockDim.x + threadIdx.x;
    if (e < NEDGES) {
        atomicAdd(&g_cnt_out[src[e]], 1);
        atomicAdd(&g_cnt_in [dst[e]], 1);
    }
}

// 3. norms = max(deg,1)^-0.5
__global__ void norms_kernel() {
    int i = blockIdx.x * blockDim.x + threadIdx.x;
    if (i < NNODES) {
        g_norm_out[i] = rsqrtf(fmaxf((float)g_cnt_out[i], 1.0f));
        g_norm_in [i] = rsqrtf(fmaxf((float)g_cnt_in [i], 1.0f));
    }
}

// 4. single-block exclusive scan of cnt_in -> row_ptr (and init cursor)
__global__ void scan_kernel() {
    __shared__ int part[1024];
    const int tid = threadIdx.x;
    const int chunk = (NNODES + 1023) >> 10;   // 40
    const int start = tid * chunk;
    int s = 0;
    for (int i = 0; i < chunk; i++) {
        int idx = start + i;
        if (idx < NNODES) s += g_cnt_in[idx];
    }
    part[tid] = s;
    __syncthreads();
    // Hillis-Steele inclusive scan
    for (int d = 1; d < 1024; d <<= 1) {
        int v = (tid >= d) ? part[tid - d] : 0;
        __syncthreads();
        part[tid] += v;
        __syncthreads();
    }
    int run = part[tid] - s;   // exclusive prefix for this chunk
    for (int i = 0; i < chunk; i++) {
        int idx = start + i;
        if (idx < NNODES) {
            g_row_ptr[idx] = run;
            g_cursor[idx]  = run;
            run += g_cnt_in[idx];
        }
    }
    if (tid == 1023) g_row_ptr[NNODES] = run;   // == NEDGES
}

// 5. scatter edges into CSR (order within a node is nondeterministic; float sums
//    differ only at ~1e-7, far below the 1e-3 tolerance)
__global__ void scatter_kernel(const int* __restrict__ src, const int* __restrict__ dst) {
    int e = blockIdx.x * blockDim.x + threadIdx.x;
    if (e < NEDGES) {
        int pos = atomicAdd(&g_cursor[dst[e]], 1);
        g_esrc[pos] = src[e];
    }
}

// ---------------------------------------------------------------------------
// 6. aggregation: one warp per destination node, no atomics.
//    agg[v] = norm_in[v] * sum_{e in CSR(v)} norm_out[src] * h[src]
// ---------------------------------------------------------------------------
__global__ void aggregate_kernel(const float* __restrict__ hin, float* __restrict__ aggout) {
    int warp = (blockIdx.x * blockDim.x + threadIdx.x) >> 5;
    int lane = threadIdx.x & 31;
    if (warp >= NNODES) return;
    const int beg = g_row_ptr[warp];
    const int end = g_row_ptr[warp + 1];
    float4 acc = make_float4(0.f, 0.f, 0.f, 0.f);
    #pragma unroll 4
    for (int e = beg; e < end; e++) {
        int s   = __ldg(&g_esrc[e]);
        float w = __ldg(&g_norm_out[s]);
        float4 x = *reinterpret_cast<const float4*>(hin + (size_t)s * D + lane * 4);
        acc.x = fmaf(w, x.x, acc.x);
        acc.y = fmaf(w, x.y, acc.y);
        acc.z = fmaf(w, x.z, acc.z);
        acc.w = fmaf(w, x.w, acc.w);
    }
    const float win = g_norm_in[warp];
    acc.x *= win; acc.y *= win; acc.z *= win; acc.w *= win;
    *reinterpret_cast<float4*>(aggout + (size_t)warp * D + lane * 4) = acc;
}

// ---------------------------------------------------------------------------
// 7. fused GEMM + bias + relu:  out[r][c] = relu(A[r][:] @ W[:][c] + b[c])
//    A: [nrows][128], W: [128][NC].  64-row tiles, 4x8 micro-tile per thread.
// ---------------------------------------------------------------------------
template <int NC>
__global__ void gemm_bias_relu_kernel(const float* __restrict__ A,
                                      const float* __restrict__ W,
                                      const float* __restrict__ bias,
                                      float* __restrict__ out) {
    constexpr int K  = 128;
    constexpr int TR = 64;
    constexpr int CG = NC / 8;              // col groups
    constexpr int NT = CG * 16;             // threads per block
    constexpr int ASTRIDE = K + 4;          // 132; 132*4B = 528 % 16 == 0 (float4 safe)

    extern __shared__ float sh[];
    float* Ws = sh;                         // K * NC
    float* As = sh + K * NC;                // TR * ASTRIDE

    const int tid  = threadIdx.x;
    const int row0 = blockIdx.x * TR;

    // stage W
    for (int i = tid; i < K * NC / 4; i += NT)
        reinterpret_cast<float4*>(Ws)[i] = reinterpret_cast<const float4*>(W)[i];
    // stage A tile (padded rows)
    for (int i = tid; i < TR * K / 4; i += NT) {
        int r  = i / (K / 4);
        int c4 = i % (K / 4);
        float4 v = reinterpret_cast<const float4*>(A + (size_t)(row0 + r) * K)[c4];
        *reinterpret_cast<float4*>(As + r * ASTRIDE + c4 * 4) = v;
    }
    __syncthreads();

    const int cx   = tid % CG;
    const int ry   = tid / CG;
    const int col0 = cx * 8;
    const int r0   = ry * 4;

    float acc[4][8];
    #pragma unroll
    for (int i = 0; i < 4; i++)
        #pragma unroll
        for (int j = 0; j < 8; j++) acc[i][j] = 0.f;

    #pragma unroll 8
    for (int k = 0; k < K; k++) {
        float a0 = As[(r0 + 0) * ASTRIDE + k];
        float a1 = As[(r0 + 1) * ASTRIDE + k];
        float a2 = As[(r0 + 2) * ASTRIDE + k];
        float a3 = As[(r0 + 3) * ASTRIDE + k];
        float4 w0 = *reinterpret_cast<float4*>(&Ws[k * NC + col0]);
        float4 w1 = *reinterpret_cast<float4*>(&Ws[k * NC + col0 + 4]);
        float wv[8] = {w0.x, w0.y, w0.z, w0.w, w1.x, w1.y, w1.z, w1.w};
        float av[4] = {a0, a1, a2, a3};
        #pragma unroll
        for (int i = 0; i < 4; i++)
            #pragma unroll
            for (int j = 0; j < 8; j++)
                acc[i][j] = fmaf(av[i], wv[j], acc[i][j]);
    }

    float bv[8];
    #pragma unroll
    for (int j = 0; j < 8; j++) bv[j] = bias[col0 + j];

    #pragma unroll
    for (int i = 0; i < 4; i++) {
        float v[8];
        #pragma unroll
        for (int j = 0; j < 8; j++) v[j] = fmaxf(acc[i][j] + bv[j], 0.f);
        float* o = out + (size_t)(row0 + r0 + i) * NC + col0;
        *reinterpret_cast<float4*>(o)     = make_float4(v[0], v[1], v[2], v[3]);
        *reinterpret_cast<float4*>(o + 4) = make_float4(v[4], v[5], v[6], v[7]);
    }
}

// ---------------------------------------------------------------------------
// 8. final linear 64 -> 10 (no relu). One warp per row, shuffle reduction.
// ---------------------------------------------------------------------------
__global__ void linear2_kernel(const float* __restrict__ T,
                               const float* __restrict__ W,   // [64][10]
                               const float* __restrict__ b,
                               float* __restrict__ out) {
    int warp = (blockIdx.x * blockDim.x + threadIdx.x) >> 5;
    int lane = threadIdx.x & 31;
    if (warp >= NNODES) return;
    float2 tv = *reinterpret_cast<const float2*>(T + (size_t)warp * DH + lane * 2);
    float s[NCLS];
    #pragma unroll
    for (int c = 0; c < NCLS; c++) {
        s[c] = tv.x * __ldg(&W[(lane * 2) * NCLS + c])
             + tv.y * __ldg(&W[(lane * 2 + 1) * NCLS + c]);
    }
    #pragma unroll
    for (int c = 0; c < NCLS; c++)
        #pragma unroll
        for (int d = 16; d > 0; d >>= 1)
            s[c] += __shfl_xor_sync(0xffffffffu, s[c], d);
    if (lane < NCLS) out[(size_t)warp * NCLS + lane] = s[lane] + b[lane];
}

// ---------------------------------------------------------------------------
// launch
// ---------------------------------------------------------------------------
extern "C" void kernel_launch(void* const* d_in, const int* in_sizes, int n_in,
                              void* d_out, int out_size) {
    const float* h   = (const float*)d_in[0];
    const int*   src = (const int*)  d_in[1];
    const int*   dst = (const int*)  d_in[2];
    const float* W0  = (const float*)d_in[3];
    const float* b0  = (const float*)d_in[4];
    const float* W1  = (const float*)d_in[5];
    const float* b1  = (const float*)d_in[6];
    const float* Wl1 = (const float*)d_in[7];
    const float* bl1 = (const float*)d_in[8];
    const float* Wl2 = (const float*)d_in[9];
    const float* bl2 = (const float*)d_in[10];
    float* out = (float*)d_out;

    // device addresses of scratch symbols (host-side query, not captured)
    void *p_agg, *p_h1, *p_h2, *p_t;
    cudaGetSymbolAddress(&p_agg, g_agg);
    cudaGetSymbolAddress(&p_h1,  g_h1);
    cudaGetSymbolAddress(&p_h2,  g_h2);
    cudaGetSymbolAddress(&p_t,   g_t);
    float* agg = (float*)p_agg;
    float* h1  = (float*)p_h1;
    float* h2  = (float*)p_h2;
    float* t   = (float*)p_t;

    constexpr int SMEM128 = (128 * 128 + 64 * 132) * 4;   // 99,328 B
    constexpr int SMEM64  = (128 * 64  + 64 * 132) * 4;   // 66,560 B
    cudaFuncSetAttribute(gemm_bias_relu_kernel<128>,
                         cudaFuncAttributeMaxDynamicSharedMemorySize, SMEM128);
    cudaFuncSetAttribute(gemm_bias_relu_kernel<64>,
                         cudaFuncAttributeMaxDynamicSharedMemorySize, SMEM64);

    const int NB_N = (NNODES + 255) / 256;
    const int NB_E = (NEDGES + 255) / 256;
    const int NB_W = (NNODES * 32 + 255) / 256;   // warp-per-node grids
    const int NB_G = NNODES / 64;                 // 625 gemm row-tiles

    // graph preprocessing (CSR by dst + symmetric norms)
    zero_counts_kernel<<<NB_N, 256>>>();
    histogram_kernel<<<NB_E, 256>>>(src, dst);
    norms_kernel<<<NB_N, 256>>>();
    scan_kernel<<<1, 1024>>>();
    scatter_kernel<<<NB_E, 256>>>(src, dst);

    // layer 0
    aggregate_kernel<<<NB_W, 256>>>(h, agg);
    gemm_bias_relu_kernel<128><<<NB_G, 256, SMEM128>>>(agg, W0, b0, h1);
    // layer 1
    aggregate_kernel<<<NB_W, 256>>>(h1, agg);
    gemm_bias_relu_kernel<128><<<NB_G, 256, SMEM128>>>(agg, W1, b1, h2);
    // MLP head
    gemm_bias_relu_kernel<64><<<NB_G, 128, SMEM64>>>(h2, Wl1, bl1, t);
    linear2_kernel<<<NB_W, 256>>>(t, Wl2, bl2, out);
}

// round 2
// speedup vs baseline: 1.4073x; 1.4073x over previous
#include <cuda_runtime.h>
#include <cuda_bf16.h>
#include <math.h>

// Problem constants
constexpr int NNODES = 40000;
constexpr int NEDGES = 640000;
constexpr int D = 128;        // feature dim (in & hidden)
constexpr int DH = 64;        // hidden//2
constexpr int NCLS = 10;

constexpr int SCAN_BLK = 512;
constexpr int NPART = (NNODES + SCAN_BLK - 1) / SCAN_BLK;   // 79

// ---------------------------------------------------------------------------
// Scratch (static device globals — no allocation at runtime)
// ---------------------------------------------------------------------------
__device__ int   g_cnt_in[NNODES];
__device__ int   g_cnt_out[NNODES];
__device__ float g_norm_in[NNODES];
__device__ float g_norm_out[NNODES];
__device__ int   g_row_ptr[NNODES + 1];
__device__ int   g_cursor[NNODES];
__device__ int   g_part[NPART];
__device__ int   g_esrc[NEDGES];          // src node of each edge, CSR by dst
__device__ float g_ew  [NEDGES];          // norm_out[src] packed alongside
__device__ float g_agg[(size_t)NNODES * D];
__device__ float g_h1 [(size_t)NNODES * D];
__device__ float g_h2 [(size_t)NNODES * D];
__device__ float g_t  [(size_t)NNODES * DH];

// ---------------------------------------------------------------------------
// 1. zero degree counters
// ---------------------------------------------------------------------------
__global__ void zero_counts_kernel() {
    int i = blockIdx.x * blockDim.x + threadIdx.x;
    if (i < NNODES) { g_cnt_in[i] = 0; g_cnt_out[i] = 0; }
}

// 2. degree histogram (also the CSR count for dst)
__global__ void histogram_kernel(const int* __restrict__ src, const int* __restrict__ dst) {
    int e = blockIdx.x * blockDim.x + threadIdx.x;
    if (e < NEDGES) {
        atomicAdd(&g_cnt_out[src[e]], 1);
        atomicAdd(&g_cnt_in [dst[e]], 1);
    }
}

// 3. norms = max(deg,1)^-0.5
__global__ void norms_kernel() {
    int i = blockIdx.x * blockDim.x + threadIdx.x;
    if (i < NNODES) {
        g_norm_out[i] = rsqrtf(fmaxf((float)g_cnt_out[i], 1.0f));
        g_norm_in [i] = rsqrtf(fmaxf((float)g_cnt_in [i], 1.0f));
    }
}

// ---------------------------------------------------------------------------
// 4a. scan pass A: per-block reduction of cnt_in -> g_part[b]
// ---------------------------------------------------------------------------
__global__ void scan_reduce_kernel() {
    const int i = blockIdx.x * SCAN_BLK + threadIdx.x;
    int v = (i < NNODES) ? g_cnt_in[i] : 0;
    #pragma unroll
    for (int d = 16; d > 0; d >>= 1) v += __shfl_xor_sync(0xffffffffu, v, d);
    __shared__ int ws[SCAN_BLK / 32];
    if ((threadIdx.x & 31) == 0) ws[threadIdx.x >> 5] = v;
    __syncthreads();
    if (threadIdx.x < SCAN_BLK / 32) {
        int s = ws[threadIdx.x];
        #pragma unroll
        for (int d = SCAN_BLK / 64; d > 0; d >>= 1)
            s += __shfl_xor_sync(0xffffu, s, d, SCAN_BLK / 32);
        if (threadIdx.x == 0) g_part[blockIdx.x] = s;
    }
}

// 4b. scan pass B: exclusive scan of NPART partials (1 small block)
__global__ void scan_part_kernel() {
    const int tid  = threadIdx.x;             // 128 threads
    const int lane = tid & 31, wid = tid >> 5;
    int v = (tid < NPART) ? g_part[tid] : 0;
    int incl = v;
    #pragma unroll
    for (int d = 1; d < 32; d <<= 1) {
        int t = __shfl_up_sync(0xffffffffu, incl, d);
        if (lane >= d) incl += t;
    }
    __shared__ int ws[4];
    if (lane == 31) ws[wid] = incl;
    __syncthreads();
    int off = 0;
    for (int w = 0; w < wid; w++) off += ws[w];
    if (tid < NPART) g_part[tid] = incl - v + off;   // exclusive
}

// 4c. scan pass C: block-level exclusive scan + partial offset -> row_ptr/cursor
__global__ void scan_apply_kernel() {
    const int i    = blockIdx.x * SCAN_BLK + threadIdx.x;
    const int lane = threadIdx.x & 31, wid = threadIdx.x >> 5;
    int v = (i < NNODES) ? g_cnt_in[i] : 0;
    int incl = v;
    #pragma unroll
    for (int d = 1; d < 32; d <<= 1) {
        int t = __shfl_up_sync(0xffffffffu, incl, d);
        if (lane >= d) incl += t;
    }
    __shared__ int ws[SCAN_BLK / 32];
    if (lane == 31) ws[wid] = incl;
    __syncthreads();
    int woff = 0;
    for (int w = 0; w < wid; w++) woff += ws[w];
    int excl = incl - v + woff + g_part[blockIdx.x];
    if (i < NNODES) { g_row_ptr[i] = excl; g_cursor[i] = excl; }
    if (i == 0) g_row_ptr[NNODES] = NEDGES;   // total is a constant
}

// 5. scatter edges into CSR, packing the edge weight norm_out[src]
__global__ void scatter_kernel(const int* __restrict__ src, const int* __restrict__ dst) {
    int e = blockIdx.x * blockDim.x + threadIdx.x;
    if (e < NEDGES) {
        int s   = src[e];
        int pos = atomicAdd(&g_cursor[dst[e]], 1);
        g_esrc[pos] = s;
        g_ew[pos]   = g_norm_out[s];
    }
}

// ---------------------------------------------------------------------------
// 6. aggregation: one warp per destination node, no atomics.
//    agg[v] = norm_in[v] * sum_{e in CSR(v)} ew[e] * h[esrc[e]]
// ---------------------------------------------------------------------------
__global__ void aggregate_kernel(const float* __restrict__ hin, float* __restrict__ aggout) {
    int warp = (blockIdx.x * blockDim.x + threadIdx.x) >> 5;
    int lane = threadIdx.x & 31;
    if (warp >= NNODES) return;
    const int beg = g_row_ptr[warp];
    const int end = g_row_ptr[warp + 1];
    float4 acc = make_float4(0.f, 0.f, 0.f, 0.f);
    #pragma unroll 4
    for (int e = beg; e < end; e++) {
        int   s = __ldg(&g_esrc[e]);
        float w = __ldg(&g_ew[e]);
        float4 x = *reinterpret_cast<const float4*>(hin + (size_t)s * D + lane * 4);
        acc.x = fmaf(w, x.x, acc.x);
        acc.y = fmaf(w, x.y, acc.y);
        acc.z = fmaf(w, x.z, acc.z);
        acc.w = fmaf(w, x.w, acc.w);
    }
    const float win = g_norm_in[warp];
    acc.x *= win; acc.y *= win; acc.z *= win; acc.w *= win;
    *reinterpret_cast<float4*>(aggout + (size_t)warp * D + lane * 4) = acc;
}

// ---------------------------------------------------------------------------
// 7. fused GEMM + bias + relu:  out[r][c] = relu(A[r][:] @ W[:][c] + b[c])
//    A: [nrows][128], W: [128][NC]. 64-row tiles, 8x8 micro-tile per thread.
// ---------------------------------------------------------------------------
template <int NC>
__global__ void __launch_bounds__((NC / 8) * 8)
gemm_bias_relu_kernel(const float* __restrict__ A,
                      const float* __restrict__ W,
                      const float* __restrict__ bias,
                      float* __restrict__ out) {
    constexpr int K  = 128;
    constexpr int TR = 64;
    constexpr int CG = NC / 8;              // col groups
    constexpr int RG = TR / 8;              // row groups (8)
    constexpr int NT = CG * RG;             // threads per block
    constexpr int ASTRIDE = K;              // broadcast reads -> no pad needed

    extern __shared__ float sh[];
    float* Ws = sh;                         // K * NC
    float* As = sh + K * NC;                // TR * ASTRIDE

    const int tid  = threadIdx.x;
    const int row0 = blockIdx.x * TR;

    // stage W
    for (int i = tid; i < K * NC / 4; i += NT)
        reinterpret_cast<float4*>(Ws)[i] = reinterpret_cast<const float4*>(W)[i];
    // stage A tile
    for (int i = tid; i < TR * K / 4; i += NT) {
        reinterpret_cast<float4*>(As)[i] =
            reinterpret_cast<const float4*>(A + (size_t)row0 * K)[i];
    }
    __syncthreads();

    const int cx   = tid % CG;
    const int ry   = tid / CG;
    const int col0 = cx * 8;
    const int r0   = ry * 8;

    float acc[8][8];
    #pragma unroll
    for (int i = 0; i < 8; i++)
        #pragma unroll
        for (int j = 0; j < 8; j++) acc[i][j] = 0.f;

    #pragma unroll 4
    for (int k = 0; k < K; k++) {
        float av[8];
        #pragma unroll
        for (int i = 0; i < 8; i++) av[i] = As[(r0 + i) * ASTRIDE + k];
        float4 w0 = *reinterpret_cast<float4*>(&Ws[k * NC + col0]);
        float4 w1 = *reinterpret_cast<float4*>(&Ws[k * NC + col0 + 4]);
        float wv[8] = {w0.x, w0.y, w0.z, w0.w, w1.x, w1.y, w1.z, w1.w};
        #pragma unroll
        for (int i = 0; i < 8; i++)
            #pragma unroll
            for (int j = 0; j < 8; j++)
                acc[i][j] = fmaf(av[i], wv[j], acc[i][j]);
    }

    float bv[8];
    #pragma unroll
    for (int j = 0; j < 8; j++) bv[j] = bias[col0 + j];

    #pragma unroll
    for (int i = 0; i < 8; i++) {
        float v[8];
        #pragma unroll
        for (int j = 0; j < 8; j++) v[j] = fmaxf(acc[i][j] + bv[j], 0.f);
        float* o = out + (size_t)(row0 + r0 + i) * NC + col0;
        *reinterpret_cast<float4*>(o)     = make_float4(v[0], v[1], v[2], v[3]);
        *reinterpret_cast<float4*>(o + 4) = make_float4(v[4], v[5], v[6], v[7]);
    }
}

// ---------------------------------------------------------------------------
// 8. final linear 64 -> 10 (no relu). One warp per row, shuffle reduction.
// ---------------------------------------------------------------------------
__global__ void linear2_kernel(const float* __restrict__ T,
                               const float* __restrict__ W,   // [64][10]
                               const float* __restrict__ b,
                               float* __restrict__ out) {
    int warp = (blockIdx.x * blockDim.x + threadIdx.x) >> 5;
    int lane = threadIdx.x & 31;
    if (warp >= NNODES) return;
    float2 tv = *reinterpret_cast<const float2*>(T + (size_t)warp * DH + lane * 2);
    float s[NCLS];
    #pragma unroll
    for (int c = 0; c < NCLS; c++) {
        s[c] = tv.x * __ldg(&W[(lane * 2) * NCLS + c])
             + tv.y * __ldg(&W[(lane * 2 + 1) * NCLS + c]);
    }
    #pragma unroll
    for (int c = 0; c < NCLS; c++)
        #pragma unroll
        for (int d = 16; d > 0; d >>= 1)
            s[c] += __shfl_xor_sync(0xffffffffu, s[c], d);
    if (lane < NCLS) out[(size_t)warp * NCLS + lane] = s[lane] + b[lane];
}

// ---------------------------------------------------------------------------
// launch
// ---------------------------------------------------------------------------
extern "C" void kernel_launch(void* const* d_in, const int* in_sizes, int n_in,
                              void* d_out, int out_size) {
    const float* h   = (const float*)d_in[0];
    const int*   src = (const int*)  d_in[1];
    const int*   dst = (const int*)  d_in[2];
    const float* W0  = (const float*)d_in[3];
    const float* b0  = (const float*)d_in[4];
    const float* W1  = (const float*)d_in[5];
    const float* b1  = (const float*)d_in[6];
    const float* Wl1 = (const float*)d_in[7];
    const float* bl1 = (const float*)d_in[8];
    const float* Wl2 = (const float*)d_in[9];
    const float* bl2 = (const float*)d_in[10];
    float* out = (float*)d_out;

    void *p_agg, *p_h1, *p_h2, *p_t;
    cudaGetSymbolAddress(&p_agg, g_agg);
    cudaGetSymbolAddress(&p_h1,  g_h1);
    cudaGetSymbolAddress(&p_h2,  g_h2);
    cudaGetSymbolAddress(&p_t,   g_t);
    float* agg = (float*)p_agg;
    float* h1  = (float*)p_h1;
    float* h2  = (float*)p_h2;
    float* t   = (float*)p_t;

    constexpr int SMEM128 = (128 * 128 + 64 * 128) * 4;   // 96 KB
    constexpr int SMEM64  = (128 * 64  + 64 * 128) * 4;   // 64 KB
    cudaFuncSetAttribute(gemm_bias_relu_kernel<128>,
                         cudaFuncAttributeMaxDynamicSharedMemorySize, SMEM128);
    cudaFuncSetAttribute(gemm_bias_relu_kernel<64>,
                         cudaFuncAttributeMaxDynamicSharedMemorySize, SMEM64);

    const int NB_N = (NNODES + 255) / 256;
    const int NB_E = (NEDGES + 255) / 256;
    const int NB_W = (NNODES * 32 + 255) / 256;   // warp-per-node grids
    const int NB_G = NNODES / 64;                 // 625 gemm row-tiles

    // graph preprocessing (CSR by dst + symmetric norms)
    zero_counts_kernel<<<NB_N, 256>>>();
    histogram_kernel<<<NB_E, 256>>>(src, dst);
    norms_kernel<<<NB_N, 256>>>();
    scan_reduce_kernel<<<NPART, SCAN_BLK>>>();
    scan_part_kernel<<<1, 128>>>();
    scan_apply_kernel<<<NPART, SCAN_BLK>>>();
    scatter_kernel<<<NB_E, 256>>>(src, dst);

    // layer 0
    aggregate_kernel<<<NB_W, 256>>>(h, agg);
    gemm_bias_relu_kernel<128><<<NB_G, 128, SMEM128>>>(agg, W0, b0, h1);
    // layer 1
    aggregate_kernel<<<NB_W, 256>>>(h1, agg);
    gemm_bias_relu_kernel<128><<<NB_G, 128, SMEM128>>>(agg, W1, b1, h2);
    // MLP head
    gemm_bias_relu_kernel<64><<<NB_G, 64, SMEM64>>>(h2, Wl1, bl1, t);
    linear2_kernel<<<NB_W, 256>>>(t, Wl2, bl2, out);
}

// round 3
// speedup vs baseline: 1.6042x; 1.1399x over previous
#include <cuda_runtime.h>
#include <cuda_bf16.h>
#include <math.h>

// Problem constants
constexpr int NNODES = 40000;
constexpr int NEDGES = 640000;
constexpr int D = 128;        // feature dim (in & hidden)
constexpr int DH = 64;        // hidden//2
constexpr int NCLS = 10;

constexpr int SCAN_BLK = 512;
constexpr int NPART = (NNODES + SCAN_BLK - 1) / SCAN_BLK;   // 79

// packed f32x2 FMA (FFMA2) — 2 IEEE fp32 fma per instruction, fma pipe
#define FMA2(d, a, b) asm("fma.rn.f32x2 %0, %1, %2, %0;" : "+l"(d) : "l"(a), "l"(b))
#define PACK2(d, x)   asm("mov.b64 %0, {%1, %1};"        : "=l"(d) : "f"(x))
#define UNPACK2(lo, hi, v) asm("mov.b64 {%0, %1}, %2;" : "=f"(lo), "=f"(hi) : "l"(v))

// ---------------------------------------------------------------------------
// Scratch (static device globals — no allocation at runtime)
// ---------------------------------------------------------------------------
__device__ int   g_cnt_in[NNODES];
__device__ int   g_cnt_out[NNODES];
__device__ float g_norm_in[NNODES];
__device__ float g_norm_out[NNODES];
__device__ int   g_row_ptr[NNODES + 1];
__device__ int   g_cursor[NNODES];
__device__ int   g_part[NPART];
__device__ int2  g_edge[NEDGES];          // {src, bitcast(norm_out[src])} CSR by dst
__device__ float g_agg[(size_t)NNODES * D];
__device__ float g_h1 [(size_t)NNODES * D];
__device__ float g_h2 [(size_t)NNODES * D];

// ---------------------------------------------------------------------------
// 1. zero degree counters
// ---------------------------------------------------------------------------
__global__ void zero_counts_kernel() {
    int i = blockIdx.x * blockDim.x + threadIdx.x;
    if (i < NNODES) { g_cnt_in[i] = 0; g_cnt_out[i] = 0; }
}

// 2. degree histogram (also the CSR count for dst)
__global__ void histogram_kernel(const int* __restrict__ src, const int* __restrict__ dst) {
    int e = blockIdx.x * blockDim.x + threadIdx.x;
    if (e < NEDGES) {
        atomicAdd(&g_cnt_out[src[e]], 1);
        atomicAdd(&g_cnt_in [dst[e]], 1);
    }
}

// ---------------------------------------------------------------------------
// 3. scan pass A: per-block reduction of cnt_in -> g_part[b]; fused norms
// ---------------------------------------------------------------------------
__global__ void scan_reduce_kernel() {
    const int i = blockIdx.x * SCAN_BLK + threadIdx.x;
    int v = 0;
    if (i < NNODES) {
        int ci = g_cnt_in[i];
        int co = g_cnt_out[i];
        v = ci;
        g_norm_in [i] = rsqrtf(fmaxf((float)ci, 1.0f));
        g_norm_out[i] = rsqrtf(fmaxf((float)co, 1.0f));
    }
    int s = v;
    #pragma unroll
    for (int d = 16; d > 0; d >>= 1) s += __shfl_xor_sync(0xffffffffu, s, d);
    __shared__ int ws[SCAN_BLK / 32];
    if ((threadIdx.x & 31) == 0) ws[threadIdx.x >> 5] = s;
    __syncthreads();
    if (threadIdx.x < SCAN_BLK / 32) {
        int t = ws[threadIdx.x];
        #pragma unroll
        for (int d = SCAN_BLK / 64; d > 0; d >>= 1)
            t += __shfl_xor_sync(0xffffu, t, d, SCAN_BLK / 32);
        if (threadIdx.x == 0) g_part[blockIdx.x] = t;
    }
}

// 3b. scan pass B: exclusive scan of NPART partials (1 small block)
__global__ void scan_part_kernel() {
    const int tid  = threadIdx.x;             // 128 threads
    const int lane = tid & 31, wid = tid >> 5;
    int v = (tid < NPART) ? g_part[tid] : 0;
    int incl = v;
    #pragma unroll
    for (int d = 1; d < 32; d <<= 1) {
        int t = __shfl_up_sync(0xffffffffu, incl, d);
        if (lane >= d) incl += t;
    }
    __shared__ int ws[4];
    if (lane == 31) ws[wid] = incl;
    __syncthreads();
    int off = 0;
    for (int w = 0; w < wid; w++) off += ws[w];
    if (tid < NPART) g_part[tid] = incl - v + off;   // exclusive
}

// 3c. scan pass C: block-level exclusive scan + partial offset -> row_ptr/cursor
__global__ void scan_apply_kernel() {
    const int i    = blockIdx.x * SCAN_BLK + threadIdx.x;
    const int lane = threadIdx.x & 31, wid = threadIdx.x >> 5;
    int v = (i < NNODES) ? g_cnt_in[i] : 0;
    int incl = v;
    #pragma unroll
    for (int d = 1; d < 32; d <<= 1) {
        int t = __shfl_up_sync(0xffffffffu, incl, d);
        if (lane >= d) incl += t;
    }
    __shared__ int ws[SCAN_BLK / 32];
    if (lane == 31) ws[wid] = incl;
    __syncthreads();
    int woff = 0;
    for (int w = 0; w < wid; w++) woff += ws[w];
    int excl = incl - v + woff + g_part[blockIdx.x];
    if (i < NNODES) { g_row_ptr[i] = excl; g_cursor[i] = excl; }
    if (i == 0) g_row_ptr[NNODES] = NEDGES;   // total is a constant
}

// 4. scatter edges into CSR, packing (src, norm_out[src]) as one 8B store
__global__ void scatter_kernel(const int* __restrict__ src, const int* __restrict__ dst) {
    int e = blockIdx.x * blockDim.x + threadIdx.x;
    if (e < NEDGES) {
        int s   = src[e];
        int pos = atomicAdd(&g_cursor[dst[e]], 1);
        g_edge[pos] = make_int2(s, __float_as_int(g_norm_out[s]));
    }
}

// ---------------------------------------------------------------------------
// 5. aggregation: one warp per destination node, no atomics.
//    agg[v] = norm_in[v] * sum_{e in CSR(v)} ew[e] * h[esrc[e]]
// ---------------------------------------------------------------------------
__global__ void aggregate_kernel(const float* __restrict__ hin, float* __restrict__ aggout) {
    int warp = (blockIdx.x * blockDim.x + threadIdx.x) >> 5;
    int lane = threadIdx.x & 31;
    if (warp >= NNODES) return;
    const int beg = g_row_ptr[warp];
    const int end = g_row_ptr[warp + 1];
    float4 acc = make_float4(0.f, 0.f, 0.f, 0.f);
    #pragma unroll 4
    for (int e = beg; e < end; e++) {
        int2  p = __ldg(&g_edge[e]);
        float w = __int_as_float(p.y);
        float4 x = *reinterpret_cast<const float4*>(hin + (size_t)p.x * D + lane * 4);
        acc.x = fmaf(w, x.x, acc.x);
        acc.y = fmaf(w, x.y, acc.y);
        acc.z = fmaf(w, x.z, acc.z);
        acc.w = fmaf(w, x.w, acc.w);
    }
    const float win = g_norm_in[warp];
    acc.x *= win; acc.y *= win; acc.z *= win; acc.w *= win;
    *reinterpret_cast<float4*>(aggout + (size_t)warp * D + lane * 4) = acc;
}

// ---------------------------------------------------------------------------
// 6. fused GEMM + bias + relu:  out[r][c] = relu(A[r][:] @ W[:][c] + b[c])
//    A:[rows][128], W:[128][128]. 64-row tiles, 8x8 micro-tile, FFMA2 k-loop.
// ---------------------------------------------------------------------------
__global__ void __launch_bounds__(128)
gemm128_bias_relu_kernel(const float* __restrict__ A,
                         const float* __restrict__ W,
                         const float* __restrict__ bias,
                         float* __restrict__ out) {
    constexpr int K  = 128;
    constexpr int NC = 128;
    constexpr int TR = 64;
    constexpr int CG = NC / 8;              // 16 col groups
    constexpr int NT = 128;

    extern __shared__ float sh[];
    float* Ws = sh;                         // K * NC
    float* As = sh + K * NC;                // TR * K

    const int tid  = threadIdx.x;
    const int row0 = blockIdx.x * TR;

    for (int i = tid; i < K * NC / 4; i += NT)
        reinterpret_cast<float4*>(Ws)[i] = reinterpret_cast<const float4*>(W)[i];
    for (int i = tid; i < TR * K / 4; i += NT)
        reinterpret_cast<float4*>(As)[i] =
            reinterpret_cast<const float4*>(A + (size_t)row0 * K)[i];
    __syncthreads();

    const int cx   = tid % CG;
    const int ry   = tid / CG;
    const int col0 = cx * 8;
    const int r0   = ry * 8;

    unsigned long long acc2[8][4];
    #pragma unroll
    for (int i = 0; i < 8; i++)
        #pragma unroll
        for (int j = 0; j < 4; j++) acc2[i][j] = 0ull;

    #pragma unroll 4
    for (int k = 0; k < K; k++) {
        ulonglong2 wA = *reinterpret_cast<ulonglong2*>(&Ws[k * NC + col0]);
        ulonglong2 wB = *reinterpret_cast<ulonglong2*>(&Ws[k * NC + col0 + 4]);
        unsigned long long wv[4] = {wA.x, wA.y, wB.x, wB.y};
        #pragma unroll
        for (int i = 0; i < 8; i++) {
            unsigned long long aa;
            PACK2(aa, As[(r0 + i) * K + k]);
            #pragma unroll
            for (int j = 0; j < 4; j++) FMA2(acc2[i][j], aa, wv[j]);
        }
    }

    float bv[8];
    #pragma unroll
    for (int j = 0; j < 8; j++) bv[j] = bias[col0 + j];

    #pragma unroll
    for (int i = 0; i < 8; i++) {
        float v[8];
        #pragma unroll
        for (int j = 0; j < 4; j++) UNPACK2(v[2 * j], v[2 * j + 1], acc2[i][j]);
        #pragma unroll
        for (int j = 0; j < 8; j++) v[j] = fmaxf(v[j] + bv[j], 0.f);
        float* o = out + (size_t)(row0 + r0 + i) * NC + col0;
        *reinterpret_cast<float4*>(o)     = make_float4(v[0], v[1], v[2], v[3]);
        *reinterpret_cast<float4*>(o + 4) = make_float4(v[4], v[5], v[6], v[7]);
    }
}

// ---------------------------------------------------------------------------
// 7. fused MLP head: t = relu(h2 @ Wl1 + bl1)  [64 wide], out = t @ Wl2 + bl2
//    64-row tiles, 64 threads, 8x8 micro-tile; t staged in smem, each thread
//    finishes one output row (10 classes).
// ---------------------------------------------------------------------------
__global__ void __launch_bounds__(64)
head_kernel(const float* __restrict__ A,      // h2 [rows][128]
            const float* __restrict__ Wl1,    // [128][64]
            const float* __restrict__ bl1,    // [64]
            const float* __restrict__ Wl2,    // [64][10]
            const float* __restrict__ bl2,    // [10]
            float* __restrict__ out) {        // [rows][10]
    constexpr int K  = 128;
    constexpr int NC = 64;
    constexpr int TR = 64;
    constexpr int CG = NC / 8;                // 8
    constexpr int NT = 64;
    constexpr int TS = 65;                    // t-stage stride (conflict-free)

    extern __shared__ float sh[];
    float* Ws = sh;                           // K*NC = 8192 floats (32KB)
    float* As = sh + K * NC;                  // TR*K = 8192 floats (32KB)
    float* Ts  = sh;                          // reuse Ws region: 64*65 = 4160
    float* W2s = sh + TR * TS;                // 640
    float* b2s = W2s + DH * NCLS;             // 10

    const int tid  = threadIdx.x;
    const int row0 = blockIdx.x * TR;

    for (int i = tid; i < K * NC / 4; i += NT)
        reinterpret_cast<float4*>(Ws)[i] = reinterpret_cast<const float4*>(Wl1)[i];
    for (int i = tid; i < TR * K / 4; i += NT)
        reinterpret_cast<float4*>(As)[i] =
            reinterpret_cast<const float4*>(A + (size_t)row0 * K)[i];
    __syncthreads();

    const int cx   = tid % CG;
    const int ry   = tid / CG;
    const int col0 = cx * 8;
    const int r0   = ry * 8;

    unsigned long long acc2[8][4];
    #pragma unroll
    for (int i = 0; i < 8; i++)
        #pragma unroll
        for (int j = 0; j < 4; j++) acc2[i][j] = 0ull;

    #pragma unroll 4
    for (int k = 0; k < K; k++) {
        ulonglong2 wA = *reinterpret_cast<ulonglong2*>(&Ws[k * NC + col0]);
        ulonglong2 wB = *reinterpret_cast<ulonglong2*>(&Ws[k * NC + col0 + 4]);
        unsigned long long wv[4] = {wA.x, wA.y, wB.x, wB.y};
        #pragma unroll
        for (int i = 0; i < 8; i++) {
            unsigned long long aa;
            PACK2(aa, As[(r0 + i) * K + k]);
            #pragma unroll
            for (int j = 0; j < 4; j++) FMA2(acc2[i][j], aa, wv[j]);
        }
    }

    float bv[8];
    #pragma unroll
    for (int j = 0; j < 8; j++) bv[j] = bl1[col0 + j];

    __syncthreads();   // everyone done reading Ws before it becomes Ts

    // write relu'd tile into Ts
    #pragma unroll
    for (int i = 0; i < 8; i++) {
        float v[8];
        #pragma unroll
        for (int j = 0; j < 4; j++) UNPACK2(v[2 * j], v[2 * j + 1], acc2[i][j]);
        #pragma unroll
        for (int j = 0; j < 8; j++)
            Ts[(r0 + i) * TS + col0 + j] = fmaxf(v[j] + bv[j], 0.f);
    }
    // stage Wl2 / bl2
    for (int i = tid; i < DH * NCLS; i += NT) W2s[i] = Wl2[i];
    if (tid < NCLS) b2s[tid] = bl2[tid];
    __syncthreads();

    // each thread: one row of the final 64->10
    float tr[DH];
    #pragma unroll 8
    for (int kk = 0; kk < DH; kk++) tr[kk] = Ts[tid * TS + kk];
    float s[NCLS];
    #pragma unroll
    for (int c = 0; c < NCLS; c++) s[c] = b2s[c];
    #pragma unroll 4
    for (int kk = 0; kk < DH; kk++) {
        float a = tr[kk];
        #pragma unroll
        for (int c = 0; c < NCLS; c++) s[c] = fmaf(a, W2s[kk * NCLS + c], s[c]);
    }
    float* o = out + (size_t)(row0 + tid) * NCLS;
    #pragma unroll
    for (int c = 0; c < NCLS; c++) o[c] = s[c];
}

// ---------------------------------------------------------------------------
// launch
// ---------------------------------------------------------------------------
extern "C" void kernel_launch(void* const* d_in, const int* in_sizes, int n_in,
                              void* d_out, int out_size) {
    const float* h   = (const float*)d_in[0];
    const int*   src = (const int*)  d_in[1];
    const int*   dst = (const int*)  d_in[2];
    const float* W0  = (const float*)d_in[3];
    const float* b0  = (const float*)d_in[4];
    const float* W1  = (const float*)d_in[5];
    const float* b1  = (const float*)d_in[6];
    const float* Wl1 = (const float*)d_in[7];
    const float* bl1 = (const float*)d_in[8];
    const float* Wl2 = (const float*)d_in[9];
    const float* bl2 = (const float*)d_in[10];
    float* out = (float*)d_out;

    void *p_agg, *p_h1, *p_h2;
    cudaGetSymbolAddress(&p_agg, g_agg);
    cudaGetSymbolAddress(&p_h1,  g_h1);
    cudaGetSymbolAddress(&p_h2,  g_h2);
    float* agg = (float*)p_agg;
    float* h1  = (float*)p_h1;
    float* h2  = (float*)p_h2;

    constexpr int SMEM128 = (128 * 128 + 64 * 128) * 4;   // 96 KB
    constexpr int SMEM64  = (128 * 64  + 64 * 128) * 4;   // 64 KB
    cudaFuncSetAttribute(gemm128_bias_relu_kernel,
                         cudaFuncAttributeMaxDynamicSharedMemorySize, SMEM128);
    cudaFuncSetAttribute(head_kernel,
                         cudaFuncAttributeMaxDynamicSharedMemorySize, SMEM64);

    const int NB_N = (NNODES + 255) / 256;
    const int NB_E = (NEDGES + 255) / 256;
    const int NB_W = (NNODES * 32 + 255) / 256;   // warp-per-node grid
    const int NB_G = NNODES / 64;                 // 625 gemm row-tiles

    // graph preprocessing (CSR by dst + symmetric norms)
    zero_counts_kernel<<<NB_N, 256>>>();
    histogram_kernel<<<NB_E, 256>>>(src, dst);
    scan_reduce_kernel<<<NPART, SCAN_BLK>>>();
    scan_part_kernel<<<1, 128>>>();
    scan_apply_kernel<<<NPART, SCAN_BLK>>>();
    scatter_kernel<<<NB_E, 256>>>(src, dst);

    // layer 0
    aggregate_kernel<<<NB_W, 256>>>(h, agg);
    gemm128_bias_relu_kernel<<<NB_G, 128, SMEM128>>>(agg, W0, b0, h1);
    // layer 1
    aggregate_kernel<<<NB_W, 256>>>(h1, agg);
    gemm128_bias_relu_kernel<<<NB_G, 128, SMEM128>>>(agg, W1, b1, h2);
    // fused MLP head (64-wide gemm + relu + 64->10 linear)
    head_kernel<<<NB_G, 64, SMEM64>>>(h2, Wl1, bl1, Wl2, bl2, out);
}

// round 4
// speedup vs baseline: 1.7374x; 1.0830x over previous
#include <cuda_runtime.h>
#include <cuda_fp16.h>
#include <math.h>

// Problem constants
constexpr int NNODES = 40000;
constexpr int NEDGES = 640000;
constexpr int D = 128;        // feature dim (in & hidden)
constexpr int DH = 64;        // hidden//2
constexpr int NCLS = 10;

constexpr int SCAN_BLK = 512;
constexpr int NPART = (NNODES + SCAN_BLK - 1) / SCAN_BLK;   // 79

// packed f32x2 FMA (FFMA2) — 2 IEEE fp32 fma per instruction, fma pipe
#define FMA2(d, a, b) asm("fma.rn.f32x2 %0, %1, %2, %0;" : "+l"(d) : "l"(a), "l"(b))
#define PACK2(d, x)   asm("mov.b64 %0, {%1, %1};"        : "=l"(d) : "f"(x))
#define UNPACK2(lo, hi, v) asm("mov.b64 {%0, %1}, %2;" : "=f"(lo), "=f"(hi) : "l"(v))

// ---------------------------------------------------------------------------
// Scratch (static device globals — no allocation at runtime)
// ---------------------------------------------------------------------------
__device__ int    g_cnt_in[NNODES];
__device__ int    g_cnt_out[NNODES];
__device__ float  g_norm_in[NNODES];
__device__ float  g_norm_out[NNODES];
__device__ int    g_row_ptr[NNODES + 1];
__device__ int    g_cursor[NNODES];
__device__ int    g_part[NPART];
__device__ int2   g_edge[NEDGES];         // {src, bitcast(norm_out[src])} CSR by dst
__device__ __half g_hf16[(size_t)NNODES * D];   // fp16 features (input conv, then h1)
__device__ float  g_agg[(size_t)NNODES * D];
__device__ float  g_h2 [(size_t)NNODES * D];

// ---------------------------------------------------------------------------
// 1. zero degree counters
// ---------------------------------------------------------------------------
__global__ void zero_counts_kernel() {
    int i = blockIdx.x * blockDim.x + threadIdx.x;
    if (i < NNODES) { g_cnt_in[i] = 0; g_cnt_out[i] = 0; }
}

// 2. degree histogram + fp32->fp16 conversion of input features (same grid:
//    NEDGES == NNODES*D/8 == 640000)
__global__ void hist_conv_kernel(const int* __restrict__ src,
                                 const int* __restrict__ dst,
                                 const float* __restrict__ h) {
    int e = blockIdx.x * blockDim.x + threadIdx.x;
    if (e < NEDGES) {
        atomicAdd(&g_cnt_out[src[e]], 1);
        atomicAdd(&g_cnt_in [dst[e]], 1);
        // convert 8 floats -> 8 halves
        const float4* s4 = reinterpret_cast<const float4*>(h);
        float4 a = __ldg(&s4[e * 2]);
        float4 b = __ldg(&s4[e * 2 + 1]);
        __half2 p0 = __floats2half2_rn(a.x, a.y);
        __half2 p1 = __floats2half2_rn(a.z, a.w);
        __half2 p2 = __floats2half2_rn(b.x, b.y);
        __half2 p3 = __floats2half2_rn(b.z, b.w);
        uint4 o;
        o.x = *reinterpret_cast<unsigned*>(&p0);
        o.y = *reinterpret_cast<unsigned*>(&p1);
        o.z = *reinterpret_cast<unsigned*>(&p2);
        o.w = *reinterpret_cast<unsigned*>(&p3);
        reinterpret_cast<uint4*>(g_hf16)[e] = o;
    }
}

// ---------------------------------------------------------------------------
// 3a. scan pass A: per-block reduction of cnt_in -> g_part[b]; fused norms
// ---------------------------------------------------------------------------
__global__ void scan_reduce_kernel() {
    const int i = blockIdx.x * SCAN_BLK + threadIdx.x;
    int v = 0;
    if (i < NNODES) {
        int ci = g_cnt_in[i];
        int co = g_cnt_out[i];
        v = ci;
        g_norm_in [i] = rsqrtf(fmaxf((float)ci, 1.0f));
        g_norm_out[i] = rsqrtf(fmaxf((float)co, 1.0f));
    }
    int s = v;
    #pragma unroll
    for (int d = 16; d > 0; d >>= 1) s += __shfl_xor_sync(0xffffffffu, s, d);
    __shared__ int ws[SCAN_BLK / 32];
    if ((threadIdx.x & 31) == 0) ws[threadIdx.x >> 5] = s;
    __syncthreads();
    if (threadIdx.x < SCAN_BLK / 32) {
        int t = ws[threadIdx.x];
        #pragma unroll
        for (int d = SCAN_BLK / 64; d > 0; d >>= 1)
            t += __shfl_xor_sync(0xffffu, t, d, SCAN_BLK / 32);
        if (threadIdx.x == 0) g_part[blockIdx.x] = t;
    }
}

// 3b. scan pass B: each block sums partials before it (no separate scan launch),
//     then block-level exclusive scan -> row_ptr/cursor
__global__ void scan_apply_kernel() {
    const int i    = blockIdx.x * SCAN_BLK + threadIdx.x;
    const int tid  = threadIdx.x;
    const int lane = tid & 31, wid = tid >> 5;
    __shared__ int ws[SCAN_BLK / 32];
    __shared__ int ow[SCAN_BLK / 32];
    __shared__ int s_off;

    // block offset = sum of g_part[j] for j < blockIdx.x
    int pv = (tid < blockIdx.x && tid < NPART) ? g_part[tid] : 0;
    #pragma unroll
    for (int d = 16; d > 0; d >>= 1) pv += __shfl_xor_sync(0xffffffffu, pv, d);
    if (lane == 0) ow[wid] = pv;
    __syncthreads();
    if (tid == 0) {
        int o = 0;
        #pragma unroll
        for (int w = 0; w < SCAN_BLK / 32; w++) o += ow[w];
        s_off = o;
    }

    // element-level scan
    int v = (i < NNODES) ? g_cnt_in[i] : 0;
    int incl = v;
    #pragma unroll
    for (int d = 1; d < 32; d <<= 1) {
        int t = __shfl_up_sync(0xffffffffu, incl, d);
        if (lane >= d) incl += t;
    }
    if (lane == 31) ws[wid] = incl;
    __syncthreads();
    int woff = 0;
    for (int w = 0; w < wid; w++) woff += ws[w];
    int excl = incl - v + woff + s_off;
    if (i < NNODES) { g_row_ptr[i] = excl; g_cursor[i] = excl; }
    if (i == 0) g_row_ptr[NNODES] = NEDGES;
}

// 4. scatter edges into CSR, packing (src, norm_out[src]) as one 8B store
__global__ void scatter_kernel(const int* __restrict__ src, const int* __restrict__ dst) {
    int e = blockIdx.x * blockDim.x + threadIdx.x;
    if (e < NEDGES) {
        int s   = src[e];
        int pos = atomicAdd(&g_cursor[dst[e]], 1);
        g_edge[pos] = make_int2(s, __float_as_int(g_norm_out[s]));
    }
}

// ---------------------------------------------------------------------------
// 5. aggregation from fp16 features: one warp per destination node, no atomics.
//    agg[v] = norm_in[v] * sum_{e in CSR(v)} ew[e] * hf16[esrc[e]]   (fp32 acc)
// ---------------------------------------------------------------------------
__global__ void aggregate_kernel(const __half* __restrict__ hin, float* __restrict__ aggout) {
    int warp = (blockIdx.x * blockDim.x + threadIdx.x) >> 5;
    int lane = threadIdx.x & 31;
    if (warp >= NNODES) return;
    const int beg = g_row_ptr[warp];
    const int end = g_row_ptr[warp + 1];
    float4 acc = make_float4(0.f, 0.f, 0.f, 0.f);
    #pragma unroll 4
    for (int e = beg; e < end; e++) {
        int2  p = __ldg(&g_edge[e]);
        float w = __int_as_float(p.y);
        uint2 q = __ldg(reinterpret_cast<const uint2*>(hin + (size_t)p.x * D) + lane);
        float2 f0 = __half22float2(*reinterpret_cast<__half2*>(&q.x));
        float2 f1 = __half22float2(*reinterpret_cast<__half2*>(&q.y));
        acc.x = fmaf(w, f0.x, acc.x);
        acc.y = fmaf(w, f0.y, acc.y);
        acc.z = fmaf(w, f1.x, acc.z);
        acc.w = fmaf(w, f1.y, acc.w);
    }
    const float win = g_norm_in[warp];
    acc.x *= win; acc.y *= win; acc.z *= win; acc.w *= win;
    *reinterpret_cast<float4*>(aggout + (size_t)warp * D + lane * 4) = acc;
}

// ---------------------------------------------------------------------------
// 6. fused GEMM + bias + relu:  out[r][c] = relu(A[r][:] @ W[:][c] + b[c])
//    A:[rows][128] fp32, W:[128][128]. 64-row tiles, 8x8 micro-tile, FFMA2.
//    HALF_OUT: write result as fp16 (feeds next aggregation).
// ---------------------------------------------------------------------------
template <bool HALF_OUT>
__global__ void __launch_bounds__(128)
gemm128_bias_relu_kernel(const float* __restrict__ A,
                         const float* __restrict__ W,
                         const float* __restrict__ bias,
                         void* __restrict__ outp) {
    constexpr int K  = 128;
    constexpr int NC = 128;
    constexpr int TR = 64;
    constexpr int CG = NC / 8;              // 16 col groups
    constexpr int NT = 128;

    extern __shared__ float sh[];
    float* Ws = sh;                         // K * NC
    float* As = sh + K * NC;                // TR * K

    const int tid  = threadIdx.x;
    const int row0 = blockIdx.x * TR;

    for (int i = tid; i < K * NC / 4; i += NT)
        reinterpret_cast<float4*>(Ws)[i] = reinterpret_cast<const float4*>(W)[i];
    for (int i = tid; i < TR * K / 4; i += NT)
        reinterpret_cast<float4*>(As)[i] =
            reinterpret_cast<const float4*>(A + (size_t)row0 * K)[i];
    __syncthreads();

    const int cx   = tid % CG;
    const int ry   = tid / CG;
    const int col0 = cx * 8;
    const int r0   = ry * 8;

    unsigned long long acc2[8][4];
    #pragma unroll
    for (int i = 0; i < 8; i++)
        #pragma unroll
        for (int j = 0; j < 4; j++) acc2[i][j] = 0ull;

    #pragma unroll 4
    for (int k = 0; k < K; k++) {
        ulonglong2 wA = *reinterpret_cast<ulonglong2*>(&Ws[k * NC + col0]);
        ulonglong2 wB = *reinterpret_cast<ulonglong2*>(&Ws[k * NC + col0 + 4]);
        unsigned long long wv[4] = {wA.x, wA.y, wB.x, wB.y};
        #pragma unroll
        for (int i = 0; i < 8; i++) {
            unsigned long long aa;
            PACK2(aa, As[(r0 + i) * K + k]);
            #pragma unroll
            for (int j = 0; j < 4; j++) FMA2(acc2[i][j], aa, wv[j]);
        }
    }

    float bv[8];
    #pragma unroll
    for (int j = 0; j < 8; j++) bv[j] = bias[col0 + j];

    #pragma unroll
    for (int i = 0; i < 8; i++) {
        float v[8];
        #pragma unroll
        for (int j = 0; j < 4; j++) UNPACK2(v[2 * j], v[2 * j + 1], acc2[i][j]);
        #pragma unroll
        for (int j = 0; j < 8; j++) v[j] = fmaxf(v[j] + bv[j], 0.f);
        if (HALF_OUT) {
            __half2 q0 = __floats2half2_rn(v[0], v[1]);
            __half2 q1 = __floats2half2_rn(v[2], v[3]);
            __half2 q2 = __floats2half2_rn(v[4], v[5]);
            __half2 q3 = __floats2half2_rn(v[6], v[7]);
            uint4 o;
            o.x = *reinterpret_cast<unsigned*>(&q0);
            o.y = *reinterpret_cast<unsigned*>(&q1);
            o.z = *reinterpret_cast<unsigned*>(&q2);
            o.w = *reinterpret_cast<unsigned*>(&q3);
            __half* ob = (__half*)outp + (size_t)(row0 + r0 + i) * NC + col0;
            *reinterpret_cast<uint4*>(ob) = o;
        } else {
            float* o = (float*)outp + (size_t)(row0 + r0 + i) * NC + col0;
            *reinterpret_cast<float4*>(o)     = make_float4(v[0], v[1], v[2], v[3]);
            *reinterpret_cast<float4*>(o + 4) = make_float4(v[4], v[5], v[6], v[7]);
        }
    }
}

// ---------------------------------------------------------------------------
// 7. fused MLP head: t = relu(h2 @ Wl1 + bl1)  [64 wide], out = t @ Wl2 + bl2
// ---------------------------------------------------------------------------
__global__ void __launch_bounds__(64)
head_kernel(const float* __restrict__ A,      // h2 [rows][128]
            const float* __restrict__ Wl1,    // [128][64]
            const float* __restrict__ bl1,    // [64]
            const float* __restrict__ Wl2,    // [64][10]
            const float* __restrict__ bl2,    // [10]
            float* __restrict__ out) {        // [rows][10]
    constexpr int K  = 128;
    constexpr int NC = 64;
    constexpr int TR = 64;
    constexpr int CG = NC / 8;                // 8
    constexpr int NT = 64;
    constexpr int TS = 65;                    // t-stage stride (conflict-free)

    extern __shared__ float sh[];
    float* Ws = sh;                           // K*NC
    float* As = sh + K * NC;                  // TR*K
    float* Ts  = sh;                          // reuse Ws region
    float* W2s = sh + TR * TS;
    float* b2s = W2s + DH * NCLS;

    const int tid  = threadIdx.x;
    const int row0 = blockIdx.x * TR;

    for (int i = tid; i < K * NC / 4; i += NT)
        reinterpret_cast<float4*>(Ws)[i] = reinterpret_cast<const float4*>(Wl1)[i];
    for (int i = tid; i < TR * K / 4; i += NT)
        reinterpret_cast<float4*>(As)[i] =
            reinterpret_cast<const float4*>(A + (size_t)row0 * K)[i];
    __syncthreads();

    const int cx   = tid % CG;
    const int ry   = tid / CG;
    const int col0 = cx * 8;
    const int r0   = ry * 8;

    unsigned long long acc2[8][4];
    #pragma unroll
    for (int i = 0; i < 8; i++)
        #pragma unroll
        for (int j = 0; j < 4; j++) acc2[i][j] = 0ull;

    #pragma unroll 4
    for (int k = 0; k < K; k++) {
        ulonglong2 wA = *reinterpret_cast<ulonglong2*>(&Ws[k * NC + col0]);
        ulonglong2 wB = *reinterpret_cast<ulonglong2*>(&Ws[k * NC + col0 + 4]);
        unsigned long long wv[4] = {wA.x, wA.y, wB.x, wB.y};
        #pragma unroll
        for (int i = 0; i < 8; i++) {
            unsigned long long aa;
            PACK2(aa, As[(r0 + i) * K + k]);
            #pragma unroll
            for (int j = 0; j < 4; j++) FMA2(acc2[i][j], aa, wv[j]);
        }
    }

    float bv[8];
    #pragma unroll
    for (int j = 0; j < 8; j++) bv[j] = bl1[col0 + j];

    __syncthreads();   // done reading Ws before it becomes Ts

    #pragma unroll
    for (int i = 0; i < 8; i++) {
        float v[8];
        #pragma unroll
        for (int j = 0; j < 4; j++) UNPACK2(v[2 * j], v[2 * j + 1], acc2[i][j]);
        #pragma unroll
        for (int j = 0; j < 8; j++)
            Ts[(r0 + i) * TS + col0 + j] = fmaxf(v[j] + bv[j], 0.f);
    }
    for (int i = tid; i < DH * NCLS; i += NT) W2s[i] = Wl2[i];
    if (tid < NCLS) b2s[tid] = bl2[tid];
    __syncthreads();

    float tr[DH];
    #pragma unroll 8
    for (int kk = 0; kk < DH; kk++) tr[kk] = Ts[tid * TS + kk];
    float s[NCLS];
    #pragma unroll
    for (int c = 0; c < NCLS; c++) s[c] = b2s[c];
    #pragma unroll 4
    for (int kk = 0; kk < DH; kk++) {
        float a = tr[kk];
        #pragma unroll
        for (int c = 0; c < NCLS; c++) s[c] = fmaf(a, W2s[kk * NCLS + c], s[c]);
    }
    float* o = out + (size_t)(row0 + tid) * NCLS;
    #pragma unroll
    for (int c = 0; c < NCLS; c++) o[c] = s[c];
}

// ---------------------------------------------------------------------------
// launch
// ---------------------------------------------------------------------------
extern "C" void kernel_launch(void* const* d_in, const int* in_sizes, int n_in,
                              void* d_out, int out_size) {
    const float* h   = (const float*)d_in[0];
    const int*   src = (const int*)  d_in[1];
    const int*   dst = (const int*)  d_in[2];
    const float* W0  = (const float*)d_in[3];
    const float* b0  = (const float*)d_in[4];
    const float* W1  = (const float*)d_in[5];
    const float* b1  = (const float*)d_in[6];
    const float* Wl1 = (const float*)d_in[7];
    const float* bl1 = (const float*)d_in[8];
    const float* Wl2 = (const float*)d_in[9];
    const float* bl2 = (const float*)d_in[10];
    float* out = (float*)d_out;

    void *p_agg, *p_hf, *p_h2;
    cudaGetSymbolAddress(&p_agg, g_agg);
    cudaGetSymbolAddress(&p_hf,  g_hf16);
    cudaGetSymbolAddress(&p_h2,  g_h2);
    float*  agg = (float*)p_agg;
    __half* hf  = (__half*)p_hf;
    float*  h2  = (float*)p_h2;

    constexpr int SMEM128 = (128 * 128 + 64 * 128) * 4;   // 96 KB
    constexpr int SMEM64  = (128 * 64  + 64 * 128) * 4;   // 64 KB
    cudaFuncSetAttribute(gemm128_bias_relu_kernel<true>,
                         cudaFuncAttributeMaxDynamicSharedMemorySize, SMEM128);
    cudaFuncSetAttribute(gemm128_bias_relu_kernel<false>,
                         cudaFuncAttributeMaxDynamicSharedMemorySize, SMEM128);
    cudaFuncSetAttribute(head_kernel,
                         cudaFuncAttributeMaxDynamicSharedMemorySize, SMEM64);

    const int NB_N = (NNODES + 255) / 256;
    const int NB_E = (NEDGES + 255) / 256;
    const int NB_W = (NNODES * 32 + 255) / 256;   // warp-per-node grid
    const int NB_G = NNODES / 64;                 // 625 gemm row-tiles

    // graph preprocessing (CSR by dst + norms) + fp16 input conversion
    zero_counts_kernel<<<NB_N, 256>>>();
    hist_conv_kernel<<<NB_E, 256>>>(src, dst, h);
    scan_reduce_kernel<<<NPART, SCAN_BLK>>>();
    scan_apply_kernel<<<NPART, SCAN_BLK>>>();
    scatter_kernel<<<NB_E, 256>>>(src, dst);

    // layer 0 (aggregate fp16 input -> fp32 agg -> GEMM -> fp16 h1 into hf)
    aggregate_kernel<<<NB_W, 256>>>(hf, agg);
    gemm128_bias_relu_kernel<true><<<NB_G, 128, SMEM128>>>(agg, W0, b0, hf);
    // layer 1
    aggregate_kernel<<<NB_W, 256>>>(hf, agg);
    gemm128_bias_relu_kernel<false><<<NB_G, 128, SMEM128>>>(agg, W1, b1, h2);
    // fused MLP head
    head_kernel<<<NB_G, 64, SMEM64>>>(h2, Wl1, bl1, Wl2, bl2, out);
}

// round 7
// speedup vs baseline: 2.4747x; 1.4244x over previous
#include <cuda_runtime.h>
#include <cuda_fp16.h>
#include <cstdint>
#include <math.h>

// Problem constants
constexpr int NNODES = 40000;
constexpr int NEDGES = 640000;
constexpr int D = 128;
constexpr int DH = 64;
constexpr int NCLS = 10;

constexpr int SCAN_BLK = 512;
constexpr int NPART = (NNODES + SCAN_BLK - 1) / SCAN_BLK;   // 79

// packed f32x2 FMA (FFMA2)
#define FMA2(d, a, b) asm("fma.rn.f32x2 %0, %1, %2, %0;" : "+l"(d) : "l"(a), "l"(b))
#define PACK2(d, x)   asm("mov.b64 %0, {%1, %1};"        : "=l"(d) : "f"(x))
#define UNPACK2(lo, hi, v) asm("mov.b64 {%0, %1}, %2;" : "=f"(lo), "=f"(hi) : "l"(v))

// warp-level tensor core ops (arch-agnostic PTX: works on plain sm_100)
#define LDSM_X4(r0, r1, r2, r3, addr)                                          \
    asm volatile("ldmatrix.sync.aligned.m8n8.x4.shared.b16 {%0,%1,%2,%3}, [%4];" \
                 : "=r"(r0), "=r"(r1), "=r"(r2), "=r"(r3) : "r"(addr))

#define MMA16816(c, a, b)                                                       \
    asm volatile("mma.sync.aligned.m16n8k16.row.col.f32.f16.f16.f32 "           \
                 "{%0,%1,%2,%3}, {%4,%5,%6,%7}, {%8,%9}, {%0,%1,%2,%3};"        \
                 : "+f"((c)[0]), "+f"((c)[1]), "+f"((c)[2]), "+f"((c)[3])       \
                 : "r"((a)[0]), "r"((a)[1]), "r"((a)[2]), "r"((a)[3]),          \
                   "r"((b)[0]), "r"((b)[1]))

// single extern shared symbol (one type for the whole TU)
extern __shared__ char smem_raw[];

// ---------------------------------------------------------------------------
// Scratch
// ---------------------------------------------------------------------------
__device__ int    g_cnt_in[NNODES];
__device__ int    g_cnt_out[NNODES];
__device__ float  g_norm_in[NNODES];
__device__ float  g_norm_out[NNODES];
__device__ int    g_row_ptr[NNODES + 1];
__device__ int    g_cursor[NNODES];
__device__ int2   g_edge[NEDGES];               // {src, bitcast(norm_out[src])}
__device__ __half g_hf16[(size_t)NNODES * D];   // fp16 features (input, then h1)
__device__ __half g_agg [(size_t)NNODES * D];   // fp16 aggregation output
__device__ float  g_h2  [(size_t)NNODES * D];

__device__ __forceinline__ uint32_t smem_u32(const void* p) {
    uint32_t a;
    asm("{ .reg .u64 t; cvta.to.shared.u64 t, %1; cvt.u32.u64 %0, t; }" : "=r"(a) : "l"(p));
    return a;
}

// ---------------------------------------------------------------------------
// 1. degree histogram + fp32->fp16 input conversion (NEDGES == NNODES*D/8)
// ---------------------------------------------------------------------------
__global__ void hist_conv_kernel(const int* __restrict__ src,
                                 const int* __restrict__ dst,
                                 const float* __restrict__ h) {
    int e = blockIdx.x * blockDim.x + threadIdx.x;
    if (e < NEDGES) {
        atomicAdd(&g_cnt_out[src[e]], 1);
        atomicAdd(&g_cnt_in [dst[e]], 1);
        const float4* s4 = reinterpret_cast<const float4*>(h);
        float4 a = __ldg(&s4[e * 2]);
        float4 b = __ldg(&s4[e * 2 + 1]);
        __half2 p0 = __floats2half2_rn(a.x, a.y);
        __half2 p1 = __floats2half2_rn(a.z, a.w);
        __half2 p2 = __floats2half2_rn(b.x, b.y);
        __half2 p3 = __floats2half2_rn(b.z, b.w);
        uint4 o;
        o.x = *reinterpret_cast<unsigned*>(&p0);
        o.y = *reinterpret_cast<unsigned*>(&p1);
        o.z = *reinterpret_cast<unsigned*>(&p2);
        o.w = *reinterpret_cast<unsigned*>(&p3);
        reinterpret_cast<uint4*>(g_hf16)[e] = o;
    }
}

// ---------------------------------------------------------------------------
// 2. one-kernel scan + norms: each block redundantly sums its prefix of cnt_in
// ---------------------------------------------------------------------------
__global__ void scan_norms_kernel() {
    const int base = blockIdx.x * SCAN_BLK;
    const int i    = base + threadIdx.x;
    const int tid  = threadIdx.x, lane = tid & 31, wid = tid >> 5;
    __shared__ int ws[SCAN_BLK / 32];
    __shared__ int s_off;

    int pv = 0;
    for (int j = tid; j < base; j += SCAN_BLK) pv += g_cnt_in[j];
    #pragma unroll
    for (int d = 16; d > 0; d >>= 1) pv += __shfl_xor_sync(0xffffffffu, pv, d);
    if (lane == 0) ws[wid] = pv;
    __syncthreads();
    if (tid == 0) {
        int o = 0;
        #pragma unroll
        for (int w = 0; w < SCAN_BLK / 32; w++) o += ws[w];
        s_off = o;
    }
    __syncthreads();

    int ci = 0;
    if (i < NNODES) {
        ci = g_cnt_in[i];
        int co = g_cnt_out[i];
        g_norm_in [i] = rsqrtf(fmaxf((float)ci, 1.0f));
        g_norm_out[i] = rsqrtf(fmaxf((float)co, 1.0f));
    }
    int incl = ci;
    #pragma unroll
    for (int d = 1; d < 32; d <<= 1) {
        int t = __shfl_up_sync(0xffffffffu, incl, d);
        if (lane >= d) incl += t;
    }
    if (lane == 31) ws[wid] = incl;
    __syncthreads();
    int woff = 0;
    for (int w = 0; w < wid; w++) woff += ws[w];
    int excl = incl - ci + woff + s_off;
    if (i < NNODES) { g_row_ptr[i] = excl; g_cursor[i] = excl; }
    if (i == 0) g_row_ptr[NNODES] = NEDGES;
}

// ---------------------------------------------------------------------------
// 3. scatter edges into CSR; re-zero counters for the next graph replay
// ---------------------------------------------------------------------------
__global__ void scatter_kernel(const int* __restrict__ src, const int* __restrict__ dst) {
    int e = blockIdx.x * blockDim.x + threadIdx.x;
    if (e < NEDGES) {
        int s   = src[e];
        int pos = atomicAdd(&g_cursor[dst[e]], 1);
        g_edge[pos] = make_int2(s, __float_as_int(g_norm_out[s]));
    }
    if (e < NNODES) { g_cnt_in[e] = 0; g_cnt_out[e] = 0; }
}

// ---------------------------------------------------------------------------
// 4. aggregation (fp16 gather, fp32 accum, fp16 out): one warp per dst node
// ---------------------------------------------------------------------------
__global__ void aggregate_kernel(const __half* __restrict__ hin, __half* __restrict__ aggout) {
    int warp = (blockIdx.x * blockDim.x + threadIdx.x) >> 5;
    int lane = threadIdx.x & 31;
    if (warp >= NNODES) return;
    const int beg = g_row_ptr[warp];
    const int end = g_row_ptr[warp + 1];
    float4 acc = make_float4(0.f, 0.f, 0.f, 0.f);
    #pragma unroll 4
    for (int e = beg; e < end; e++) {
        int2  p = __ldg(&g_edge[e]);
        float w = __int_as_float(p.y);
        uint2 q = __ldg(reinterpret_cast<const uint2*>(hin + (size_t)p.x * D) + lane);
        float2 f0 = __half22float2(*reinterpret_cast<__half2*>(&q.x));
        float2 f1 = __half22float2(*reinterpret_cast<__half2*>(&q.y));
        acc.x = fmaf(w, f0.x, acc.x);
        acc.y = fmaf(w, f0.y, acc.y);
        acc.z = fmaf(w, f1.x, acc.z);
        acc.w = fmaf(w, f1.y, acc.w);
    }
    const float win = g_norm_in[warp];
    __half2 p0 = __floats2half2_rn(acc.x * win, acc.y * win);
    __half2 p1 = __floats2half2_rn(acc.z * win, acc.w * win);
    uint2 o;
    o.x = *reinterpret_cast<unsigned*>(&p0);
    o.y = *reinterpret_cast<unsigned*>(&p1);
    *(reinterpret_cast<uint2*>(aggout + (size_t)warp * D) + lane) = o;
}

// ---------------------------------------------------------------------------
// 5. HMMA GEMM + bias + relu: D[128t x 128] = A[128t x 128] @ W[128][128]
//    A fp16 (agg), B = W^T fp16 in smem. mma.sync m16n8k16 + ldmatrix.
//    8 warps, warp tile 32x64.
// ---------------------------------------------------------------------------
constexpr int MMS = 136;                           // smem row stride in halves (pad)
constexpr int MM_SMEM_BYTES = 2 * 128 * MMS * 2;   // As + Bs = 69632 B

template <bool HALF_OUT>
__global__ void __launch_bounds__(256)
mma_gemm_kernel(const __half* __restrict__ A,    // [NNODES][128] fp16
                const float* __restrict__ W,     // [128][128] fp32
                const float* __restrict__ bias,  // [128]
                void* __restrict__ outp) {
    __half* As = reinterpret_cast<__half*>(smem_raw);      // [128][MMS]
    __half* Bs = As + 128 * MMS;                           // [128][MMS] (Bs[n][k]=W[k][n])

    const int tid  = threadIdx.x;
    const int wid  = tid >> 5;
    const int lane = tid & 31;
    const int row0 = blockIdx.x * 128;

    // stage A (zero-pad rows past NNODES)
    for (int idx = tid; idx < 2048; idx += 256) {
        int r  = idx >> 4;
        int c8 = (idx & 15) << 3;
        uint4 v = make_uint4(0u, 0u, 0u, 0u);
        if (row0 + r < NNODES)
            v = *reinterpret_cast<const uint4*>(A + (size_t)(row0 + r) * D + c8);
        *reinterpret_cast<uint4*>(&As[r * MMS + c8]) = v;
    }
    // stage B = W^T as fp16 (W is L2-resident after first tile)
    for (int idx = tid; idx < 2048; idx += 256) {
        int n  = idx & 127;
        int k0 = (idx >> 7) << 3;
        __half hv[8];
        #pragma unroll
        for (int j = 0; j < 8; j++) hv[j] = __float2half(__ldg(&W[(k0 + j) * D + n]));
        *reinterpret_cast<uint4*>(&Bs[n * MMS + k0]) = *reinterpret_cast<uint4*>(hv);
    }
    __syncthreads();

    const int warpM = wid & 3;        // 0..3 -> m 0,32,64,96
    const int warpN = wid >> 2;       // 0..1 -> n 0,64

    // per-lane ldmatrix base addresses
    const uint32_t sbA = smem_u32(As);
    const uint32_t sbB = smem_u32(Bs);
    // A x4: lanes 0-7 rows+0..7 @k, 8-15 rows+8..15 @k, 16-23 rows+0..7 @k+8, 24-31 rows+8..15 @k+8
    const int arow = warpM * 32 + (((lane >> 3) & 1) << 3) + (lane & 7);
    const int acol = (lane >> 4) << 3;
    uint32_t aaddr = sbA + (uint32_t)(arow * MMS + acol) * 2;
    // B x4 covers 2 n-tiles x k16: lanes 0-7 n+0..7 @k, 8-15 n+0..7 @k+8, 16-23 n+8..15 @k, 24-31 n+8..15 @k+8
    const int brow = warpN * 64 + ((lane >> 4) << 3) + (lane & 7);
    const int bcol = lane & 8;
    uint32_t baddr = sbB + (uint32_t)(brow * MMS + bcol) * 2;

    float acc[2][8][4];
    #pragma unroll
    for (int mi = 0; mi < 2; mi++)
        #pragma unroll
        for (int ni = 0; ni < 8; ni++)
            #pragma unroll
            for (int q = 0; q < 4; q++) acc[mi][ni][q] = 0.f;

    #pragma unroll
    for (int ks = 0; ks < 8; ks++) {
        const uint32_t koff = (uint32_t)ks * 32;   // 16 halves = 32 B
        uint32_t a[2][4];
        LDSM_X4(a[0][0], a[0][1], a[0][2], a[0][3], aaddr + koff);
        LDSM_X4(a[1][0], a[1][1], a[1][2], a[1][3], aaddr + koff + (uint32_t)(16 * MMS * 2));
        uint32_t b[8][2];
        #pragma unroll
        for (int g = 0; g < 4; g++) {
            LDSM_X4(b[g * 2][0], b[g * 2][1], b[g * 2 + 1][0], b[g * 2 + 1][1],
                    baddr + koff + (uint32_t)(g * 16 * MMS * 2));
        }
        #pragma unroll
        for (int mi = 0; mi < 2; mi++)
            #pragma unroll
            for (int ni = 0; ni < 8; ni++)
                MMA16816(acc[mi][ni], a[mi], b[ni]);
    }

    // epilogue: c0,c1 -> row m+gid, cols 2*tig,+1; c2,c3 -> row +8
    const int gid = lane >> 2;
    const int tig = lane & 3;
    #pragma unroll
    for (int mi = 0; mi < 2; mi++) {
        const int r_lo = row0 + warpM * 32 + mi * 16 + gid;
        #pragma unroll
        for (int half = 0; half < 2; half++) {
            const int orow = r_lo + half * 8;
            if (orow >= NNODES) continue;
            #pragma unroll
            for (int ni = 0; ni < 8; ni++) {
                const int col = warpN * 64 + ni * 8 + tig * 2;
                float v0 = acc[mi][ni][half * 2 + 0] + __ldg(&bias[col]);
                float v1 = acc[mi][ni][half * 2 + 1] + __ldg(&bias[col + 1]);
                v0 = fmaxf(v0, 0.f);
                v1 = fmaxf(v1, 0.f);
                if (HALF_OUT) {
                    __half2 q = __floats2half2_rn(v0, v1);
                    *reinterpret_cast<__half2*>((__half*)outp + (size_t)orow * D + col) = q;
                } else {
                    *reinterpret_cast<float2*>((float*)outp + (size_t)orow * D + col) =
                        make_float2(v0, v1);
                }
            }
        }
    }
}

// ---------------------------------------------------------------------------
// 6. fused MLP head (FFMA2): t = relu(h2 @ Wl1 + bl1), out = t @ Wl2 + bl2
// ---------------------------------------------------------------------------
__global__ void __launch_bounds__(64)
head_kernel(const float* __restrict__ A,
            const float* __restrict__ Wl1,
            const float* __restrict__ bl1,
            const float* __restrict__ Wl2,
            const float* __restrict__ bl2,
            float* __restrict__ out) {
    constexpr int K  = 128;
    constexpr int NC = 64;
    constexpr int TR = 64;
    constexpr int CG = NC / 8;
    constexpr int NT = 64;
    constexpr int TS = 65;

    float* sh = reinterpret_cast<float*>(smem_raw);
    float* Ws = sh;
    float* As = sh + K * NC;
    float* Ts  = sh;
    float* W2s = sh + TR * TS;
    float* b2s = W2s + DH * NCLS;

    const int tid  = threadIdx.x;
    const int row0 = blockIdx.x * TR;

    for (int i = tid; i < K * NC / 4; i += NT)
        reinterpret_cast<float4*>(Ws)[i] = reinterpret_cast<const float4*>(Wl1)[i];
    for (int i = tid; i < TR * K / 4; i += NT)
        reinterpret_cast<float4*>(As)[i] =
            reinterpret_cast<const float4*>(A + (size_t)row0 * K)[i];
    __syncthreads();

    const int cx   = tid % CG;
    const int ry   = tid / CG;
    const int col0 = cx * 8;
    const int r0   = ry * 8;

    unsigned long long acc2[8][4];
    #pragma unroll
    for (int i = 0; i < 8; i++)
        #pragma unroll
        for (int j = 0; j < 4; j++) acc2[i][j] = 0ull;

    #pragma unroll 4
    for (int k = 0; k < K; k++) {
        ulonglong2 wA = *reinterpret_cast<ulonglong2*>(&Ws[k * NC + col0]);
        ulonglong2 wB = *reinterpret_cast<ulonglong2*>(&Ws[k * NC + col0 + 4]);
        unsigned long long wv[4] = {wA.x, wA.y, wB.x, wB.y};
        #pragma unroll
        for (int i = 0; i < 8; i++) {
            unsigned long long aa;
            PACK2(aa, As[(r0 + i) * K + k]);
            #pragma unroll
            for (int j = 0; j < 4; j++) FMA2(acc2[i][j], aa, wv[j]);
        }
    }

    float bv[8];
    #pragma unroll
    for (int j = 0; j < 8; j++) bv[j] = bl1[col0 + j];

    __syncthreads();

    #pragma unroll
    for (int i = 0; i < 8; i++) {
        float v[8];
        #pragma unroll
        for (int j = 0; j < 4; j++) UNPACK2(v[2 * j], v[2 * j + 1], acc2[i][j]);
        #pragma unroll
        for (int j = 0; j < 8; j++)
            Ts[(r0 + i) * TS + col0 + j] = fmaxf(v[j] + bv[j], 0.f);
    }
    for (int i = tid; i < DH * NCLS; i += NT) W2s[i] = Wl2[i];
    if (tid < NCLS) b2s[tid] = bl2[tid];
    __syncthreads();

    float tr[DH];
    #pragma unroll 8
    for (int kk = 0; kk < DH; kk++) tr[kk] = Ts[tid * TS + kk];
    float s[NCLS];
    #pragma unroll
    for (int c = 0; c < NCLS; c++) s[c] = b2s[c];
    #pragma unroll 4
    for (int kk = 0; kk < DH; kk++) {
        float a = tr[kk];
        #pragma unroll
        for (int c = 0; c < NCLS; c++) s[c] = fmaf(a, W2s[kk * NCLS + c], s[c]);
    }
    float* o = out + (size_t)(row0 + tid) * NCLS;
    #pragma unroll
    for (int c = 0; c < NCLS; c++) o[c] = s[c];
}

// ---------------------------------------------------------------------------
// launch
// ---------------------------------------------------------------------------
extern "C" void kernel_launch(void* const* d_in, const int* in_sizes, int n_in,
                              void* d_out, int out_size) {
    const float* h   = (const float*)d_in[0];
    const int*   src = (const int*)  d_in[1];
    const int*   dst = (const int*)  d_in[2];
    const float* W0  = (const float*)d_in[3];
    const float* b0  = (const float*)d_in[4];
    const float* W1  = (const float*)d_in[5];
    const float* b1  = (const float*)d_in[6];
    const float* Wl1 = (const float*)d_in[7];
    const float* bl1 = (const float*)d_in[8];
    const float* Wl2 = (const float*)d_in[9];
    const float* bl2 = (const float*)d_in[10];
    float* out = (float*)d_out;

    void *p_agg, *p_hf, *p_h2;
    cudaGetSymbolAddress(&p_agg, g_agg);
    cudaGetSymbolAddress(&p_hf,  g_hf16);
    cudaGetSymbolAddress(&p_h2,  g_h2);
    __half* agg = (__half*)p_agg;
    __half* hf  = (__half*)p_hf;
    float*  h2  = (float*)p_h2;

    constexpr int SMEM_HEAD = (128 * 64 + 64 * 128) * 4;   // 64 KB
    cudaFuncSetAttribute(mma_gemm_kernel<true>,
                         cudaFuncAttributeMaxDynamicSharedMemorySize, MM_SMEM_BYTES);
    cudaFuncSetAttribute(mma_gemm_kernel<false>,
                         cudaFuncAttributeMaxDynamicSharedMemorySize, MM_SMEM_BYTES);
    cudaFuncSetAttribute(head_kernel,
                         cudaFuncAttributeMaxDynamicSharedMemorySize, SMEM_HEAD);

    const int NB_E = (NEDGES + 255) / 256;
    const int NB_W = (NNODES * 32 + 255) / 256;       // warp-per-node grid
    const int NB_M = (NNODES + 127) / 128;            // 313 MMA tiles
    const int NB_H = NNODES / 64;                     // 625 head tiles

    // preprocessing: 3 launches
    hist_conv_kernel<<<NB_E, 256>>>(src, dst, h);
    scan_norms_kernel<<<NPART, SCAN_BLK>>>();
    scatter_kernel<<<NB_E, 256>>>(src, dst);

    // layer 0
    aggregate_kernel<<<NB_W, 256>>>(hf, agg);
    mma_gemm_kernel<true><<<NB_M, 256, MM_SMEM_BYTES>>>(agg, W0, b0, hf);
    // layer 1
    aggregate_kernel<<<NB_W, 256>>>(hf, agg);
    mma_gemm_kernel<false><<<NB_M, 256, MM_SMEM_BYTES>>>(agg, W1, b1, h2);
    // MLP head
    head_kernel<<<NB_H, 64, SMEM_HEAD>>>(h2, Wl1, bl1, Wl2, bl2, out);
}

// round 8
// speedup vs baseline: 3.0866x; 1.2473x over previous
#include <cuda_runtime.h>
#include <cuda_fp16.h>
#include <cstdint>
#include <math.h>

// Problem constants
constexpr int NNODES = 40000;
constexpr int NEDGES = 640000;
constexpr int D = 128;
constexpr int DH = 64;
constexpr int NCLS = 10;

constexpr int SCAN_BLK = 512;
constexpr int NPART = (NNODES + SCAN_BLK - 1) / SCAN_BLK;   // 79

// packed f32x2 FMA (FFMA2)
#define FMA2(d, a, b)  asm("fma.rn.f32x2 %0, %1, %2, %0;" : "+l"(d) : "l"(a), "l"(b))
#define PACK2(d, x)    asm("mov.b64 %0, {%1, %1};"        : "=l"(d) : "f"(x))
#define PACK2F(d, x, y) asm("mov.b64 %0, {%1, %2};"       : "=l"(d) : "f"(x), "f"(y))
#define UNPACK2(lo, hi, v) asm("mov.b64 {%0, %1}, %2;" : "=f"(lo), "=f"(hi) : "l"(v))

// warp-level tensor core ops (arch-agnostic PTX: works on plain sm_100)
#define LDSM_X4(r0, r1, r2, r3, addr)                                          \
    asm volatile("ldmatrix.sync.aligned.m8n8.x4.shared.b16 {%0,%1,%2,%3}, [%4];" \
                 : "=r"(r0), "=r"(r1), "=r"(r2), "=r"(r3) : "r"(addr))

#define MMA16816(c, a, b)                                                       \
    asm volatile("mma.sync.aligned.m16n8k16.row.col.f32.f16.f16.f32 "           \
                 "{%0,%1,%2,%3}, {%4,%5,%6,%7}, {%8,%9}, {%0,%1,%2,%3};"        \
                 : "+f"((c)[0]), "+f"((c)[1]), "+f"((c)[2]), "+f"((c)[3])       \
                 : "r"((a)[0]), "r"((a)[1]), "r"((a)[2]), "r"((a)[3]),          \
                   "r"((b)[0]), "r"((b)[1]))

// single extern shared symbol (one type for the whole TU)
extern __shared__ char smem_raw[];

// ---------------------------------------------------------------------------
// Scratch
// ---------------------------------------------------------------------------
__device__ int    g_cnt_in[NNODES];
__device__ int    g_cnt_out[NNODES];
__device__ float  g_norm_in[NNODES];
__device__ float  g_norm_out[NNODES];
__device__ int    g_row_ptr[NNODES + 1];
__device__ int    g_cursor[NNODES];
__device__ int2   g_edge[NEDGES];               // {src, bitcast(norm_out[src])}
__device__ __half g_hf16[(size_t)NNODES * D];   // fp16 features (input -> h1 -> h2)
__device__ __half g_agg [(size_t)NNODES * D];   // fp16 aggregation output

__device__ __forceinline__ uint32_t smem_u32(const void* p) {
    uint32_t a;
    asm("{ .reg .u64 t; cvta.to.shared.u64 t, %1; cvt.u32.u64 %0, t; }" : "=r"(a) : "l"(p));
    return a;
}

// ---------------------------------------------------------------------------
// 1. degree histogram + fp32->fp16 input conversion (NEDGES == NNODES*D/8)
// ---------------------------------------------------------------------------
__global__ void hist_conv_kernel(const int* __restrict__ src,
                                 const int* __restrict__ dst,
                                 const float* __restrict__ h) {
    int e = blockIdx.x * blockDim.x + threadIdx.x;
    if (e < NEDGES) {
        atomicAdd(&g_cnt_out[src[e]], 1);
        atomicAdd(&g_cnt_in [dst[e]], 1);
        const float4* s4 = reinterpret_cast<const float4*>(h);
        float4 a = __ldg(&s4[e * 2]);
        float4 b = __ldg(&s4[e * 2 + 1]);
        __half2 p0 = __floats2half2_rn(a.x, a.y);
        __half2 p1 = __floats2half2_rn(a.z, a.w);
        __half2 p2 = __floats2half2_rn(b.x, b.y);
        __half2 p3 = __floats2half2_rn(b.z, b.w);
        uint4 o;
        o.x = *reinterpret_cast<unsigned*>(&p0);
        o.y = *reinterpret_cast<unsigned*>(&p1);
        o.z = *reinterpret_cast<unsigned*>(&p2);
        o.w = *reinterpret_cast<unsigned*>(&p3);
        reinterpret_cast<uint4*>(g_hf16)[e] = o;
    }
}

// ---------------------------------------------------------------------------
// 2. one-kernel scan + norms: each block redundantly sums its prefix of cnt_in
// ---------------------------------------------------------------------------
__global__ void scan_norms_kernel() {
    const int base = blockIdx.x * SCAN_BLK;
    const int i    = base + threadIdx.x;
    const int tid  = threadIdx.x, lane = tid & 31, wid = tid >> 5;
    __shared__ int ws[SCAN_BLK / 32];
    __shared__ int s_off;

    int pv = 0;
    for (int j = tid; j < base; j += SCAN_BLK) pv += g_cnt_in[j];
    #pragma unroll
    for (int d = 16; d > 0; d >>= 1) pv += __shfl_xor_sync(0xffffffffu, pv, d);
    if (lane == 0) ws[wid] = pv;
    __syncthreads();
    if (tid == 0) {
        int o = 0;
        #pragma unroll
        for (int w = 0; w < SCAN_BLK / 32; w++) o += ws[w];
        s_off = o;
    }
    __syncthreads();

    int ci = 0;
    if (i < NNODES) {
        ci = g_cnt_in[i];
        int co = g_cnt_out[i];
        g_norm_in [i] = rsqrtf(fmaxf((float)ci, 1.0f));
        g_norm_out[i] = rsqrtf(fmaxf((float)co, 1.0f));
    }
    int incl = ci;
    #pragma unroll
    for (int d = 1; d < 32; d <<= 1) {
        int t = __shfl_up_sync(0xffffffffu, incl, d);
        if (lane >= d) incl += t;
    }
    if (lane == 31) ws[wid] = incl;
    __syncthreads();
    int woff = 0;
    for (int w = 0; w < wid; w++) woff += ws[w];
    int excl = incl - ci + woff + s_off;
    if (i < NNODES) { g_row_ptr[i] = excl; g_cursor[i] = excl; }
    if (i == 0) g_row_ptr[NNODES] = NEDGES;
}

// ---------------------------------------------------------------------------
// 3. scatter edges into CSR; re-zero counters for the next graph replay
// ---------------------------------------------------------------------------
__global__ void scatter_kernel(const int* __restrict__ src, const int* __restrict__ dst) {
    int e = blockIdx.x * blockDim.x + threadIdx.x;
    if (e < NEDGES) {
        int s   = src[e];
        int pos = atomicAdd(&g_cursor[dst[e]], 1);
        g_edge[pos] = make_int2(s, __float_as_int(g_norm_out[s]));
    }
    if (e < NNODES) { g_cnt_in[e] = 0; g_cnt_out[e] = 0; }
}

// ---------------------------------------------------------------------------
// 4. aggregation: HALF-WARP (16 lanes) per node; uint4 (8 halves) per lane.
//    Edge indices loaded coalesced in chunks of 16, broadcast via shfl w=16.
//    fp32 (f32x2) accumulation, fp16 out.
// ---------------------------------------------------------------------------
__device__ __forceinline__ void agg_accum(unsigned long long acc[4], uint4 q, float w) {
    unsigned long long ww;
    PACK2(ww, w);
    float2 f0 = __half22float2(*reinterpret_cast<__half2*>(&q.x));
    float2 f1 = __half22float2(*reinterpret_cast<__half2*>(&q.y));
    float2 f2 = __half22float2(*reinterpret_cast<__half2*>(&q.z));
    float2 f3 = __half22float2(*reinterpret_cast<__half2*>(&q.w));
    unsigned long long v0, v1, v2, v3;
    PACK2F(v0, f0.x, f0.y);
    PACK2F(v1, f1.x, f1.y);
    PACK2F(v2, f2.x, f2.y);
    PACK2F(v3, f3.x, f3.y);
    FMA2(acc[0], ww, v0);
    FMA2(acc[1], ww, v1);
    FMA2(acc[2], ww, v2);
    FMA2(acc[3], ww, v3);
}

__global__ void aggregate_kernel(const __half* __restrict__ hin, __half* __restrict__ aggout) {
    const int gw = (blockIdx.x * blockDim.x + threadIdx.x) >> 4;   // node
    const int sl = threadIdx.x & 15;                               // sublane
    if (gw >= NNODES) return;
    const unsigned hm = (threadIdx.x & 16) ? 0xFFFF0000u : 0x0000FFFFu;  // half-warp mask
    const int beg = g_row_ptr[gw];
    const int end = g_row_ptr[gw + 1];

    unsigned long long acc[4] = {0ull, 0ull, 0ull, 0ull};
    const uint4* feat = reinterpret_cast<const uint4*>(hin);

    for (int base = beg; base < end; base += 16) {
        const int n = min(16, end - base);
        int2 my = make_int2(0, 0);
        if (base + sl < end) my = __ldg(&g_edge[base + sl]);
        int j = 0;
        for (; j + 2 <= n; j += 2) {
            int   s0 = __shfl_sync(hm, my.x, j, 16);
            float w0 = __int_as_float(__shfl_sync(hm, my.y, j, 16));
            int   s1 = __shfl_sync(hm, my.x, j + 1, 16);
            float w1 = __int_as_float(__shfl_sync(hm, my.y, j + 1, 16));
            uint4 q0 = __ldg(feat + (size_t)s0 * 16 + sl);
            uint4 q1 = __ldg(feat + (size_t)s1 * 16 + sl);
            agg_accum(acc, q0, w0);
            agg_accum(acc, q1, w1);
        }
        if (j < n) {
            int   s0 = __shfl_sync(hm, my.x, j, 16);
            float w0 = __int_as_float(__shfl_sync(hm, my.y, j, 16));
            uint4 q0 = __ldg(feat + (size_t)s0 * 16 + sl);
            agg_accum(acc, q0, w0);
        }
    }

    const float win = g_norm_in[gw];
    float v[8];
    UNPACK2(v[0], v[1], acc[0]);
    UNPACK2(v[2], v[3], acc[1]);
    UNPACK2(v[4], v[5], acc[2]);
    UNPACK2(v[6], v[7], acc[3]);
    __half2 p0 = __floats2half2_rn(v[0] * win, v[1] * win);
    __half2 p1 = __floats2half2_rn(v[2] * win, v[3] * win);
    __half2 p2 = __floats2half2_rn(v[4] * win, v[5] * win);
    __half2 p3 = __floats2half2_rn(v[6] * win, v[7] * win);
    uint4 o;
    o.x = *reinterpret_cast<unsigned*>(&p0);
    o.y = *reinterpret_cast<unsigned*>(&p1);
    o.z = *reinterpret_cast<unsigned*>(&p2);
    o.w = *reinterpret_cast<unsigned*>(&p3);
    reinterpret_cast<uint4*>(aggout)[(size_t)gw * 16 + sl] = o;
}

// ---------------------------------------------------------------------------
// 5. HMMA GEMM + bias + relu: D[128t x 128] = A[128t x 128] @ W[128][128]
//    A fp16 (agg), B = W^T fp16 in smem. 8 warps, warp tile 32x64. fp16 out.
// ---------------------------------------------------------------------------
constexpr int MMS = 136;                           // smem row stride in halves (pad)
constexpr int MM_SMEM_BYTES = 2 * 128 * MMS * 2;   // As + Bs = 69632 B

__global__ void __launch_bounds__(256)
mma_gemm_kernel(const __half* __restrict__ A,    // [NNODES][128] fp16
                const float* __restrict__ W,     // [128][128] fp32
                const float* __restrict__ bias,  // [128]
                __half* __restrict__ outp) {     // [NNODES][128] fp16
    __half* As = reinterpret_cast<__half*>(smem_raw);      // [128][MMS]
    __half* Bs = As + 128 * MMS;                           // [128][MMS] (Bs[n][k]=W[k][n])

    const int tid  = threadIdx.x;
    const int wid  = tid >> 5;
    const int lane = tid & 31;
    const int row0 = blockIdx.x * 128;

    // stage A (zero-pad rows past NNODES)
    for (int idx = tid; idx < 2048; idx += 256) {
        int r  = idx >> 4;
        int c8 = (idx & 15) << 3;
        uint4 v = make_uint4(0u, 0u, 0u, 0u);
        if (row0 + r < NNODES)
            v = *reinterpret_cast<const uint4*>(A + (size_t)(row0 + r) * D + c8);
        *reinterpret_cast<uint4*>(&As[r * MMS + c8]) = v;
    }
    // stage B = W^T as fp16
    for (int idx = tid; idx < 2048; idx += 256) {
        int n  = idx & 127;
        int k0 = (idx >> 7) << 3;
        __half hv[8];
        #pragma unroll
        for (int j = 0; j < 8; j++) hv[j] = __float2half(__ldg(&W[(k0 + j) * D + n]));
        *reinterpret_cast<uint4*>(&Bs[n * MMS + k0]) = *reinterpret_cast<uint4*>(hv);
    }
    __syncthreads();

    const int warpM = wid & 3;
    const int warpN = wid >> 2;

    const uint32_t sbA = smem_u32(As);
    const uint32_t sbB = smem_u32(Bs);
    const int arow = warpM * 32 + (((lane >> 3) & 1) << 3) + (lane & 7);
    const int acol = (lane >> 4) << 3;
    uint32_t aaddr = sbA + (uint32_t)(arow * MMS + acol) * 2;
    const int brow = warpN * 64 + ((lane >> 4) << 3) + (lane & 7);
    const int bcol = lane & 8;
    uint32_t baddr = sbB + (uint32_t)(brow * MMS + bcol) * 2;

    float acc[2][8][4];
    #pragma unroll
    for (int mi = 0; mi < 2; mi++)
        #pragma unroll
        for (int ni = 0; ni < 8; ni++)
            #pragma unroll
            for (int q = 0; q < 4; q++) acc[mi][ni][q] = 0.f;

    #pragma unroll
    for (int ks = 0; ks < 8; ks++) {
        const uint32_t koff = (uint32_t)ks * 32;
        uint32_t a[2][4];
        LDSM_X4(a[0][0], a[0][1], a[0][2], a[0][3], aaddr + koff);
        LDSM_X4(a[1][0], a[1][1], a[1][2], a[1][3], aaddr + koff + (uint32_t)(16 * MMS * 2));
        uint32_t b[8][2];
        #pragma unroll
        for (int g = 0; g < 4; g++) {
            LDSM_X4(b[g * 2][0], b[g * 2][1], b[g * 2 + 1][0], b[g * 2 + 1][1],
                    baddr + koff + (uint32_t)(g * 16 * MMS * 2));
        }
        #pragma unroll
        for (int mi = 0; mi < 2; mi++)
            #pragma unroll
            for (int ni = 0; ni < 8; ni++)
                MMA16816(acc[mi][ni], a[mi], b[ni]);
    }

    const int gid = lane >> 2;
    const int tig = lane & 3;
    #pragma unroll
    for (int mi = 0; mi < 2; mi++) {
        const int r_lo = row0 + warpM * 32 + mi * 16 + gid;
        #pragma unroll
        for (int half = 0; half < 2; half++) {
            const int orow = r_lo + half * 8;
            if (orow >= NNODES) continue;
            #pragma unroll
            for (int ni = 0; ni < 8; ni++) {
                const int col = warpN * 64 + ni * 8 + tig * 2;
                float v0 = fmaxf(acc[mi][ni][half * 2 + 0] + __ldg(&bias[col]), 0.f);
                float v1 = fmaxf(acc[mi][ni][half * 2 + 1] + __ldg(&bias[col + 1]), 0.f);
                __half2 q = __floats2half2_rn(v0, v1);
                *reinterpret_cast<__half2*>(outp + (size_t)orow * D + col) = q;
            }
        }
    }
}

// ---------------------------------------------------------------------------
// 6. fused HMMA MLP head: t = relu(h2f @ Wl1 + bl1) [64], out = t @ Wl2 + bl2
//    128 threads (4 warps), 64-row tiles, warp tile m16 x n64.
// ---------------------------------------------------------------------------
constexpr int HD_SMEM_BYTES = 2 * 64 * MMS * 2;   // As + Bs = 34816 B

__global__ void __launch_bounds__(128)
head_kernel(const __half* __restrict__ A,     // h2 [NNODES][128] fp16
            const float* __restrict__ Wl1,    // [128][64]
            const float* __restrict__ bl1,    // [64]
            const float* __restrict__ Wl2,    // [64][10]
            const float* __restrict__ bl2,    // [10]
            float* __restrict__ out) {        // [NNODES][10]
    __half* As = reinterpret_cast<__half*>(smem_raw);   // [64][MMS]
    __half* Bs = As + 64 * MMS;                         // [64][MMS] (Bs[n][k]=Wl1[k][n])
    // phase-2 overlays (after MMA)
    float* Ts  = reinterpret_cast<float*>(smem_raw);    // [64][65]
    float* W2s = Ts + 64 * 65;                          // [64*10]
    float* b2s = W2s + DH * NCLS;                       // [10]

    const int tid  = threadIdx.x;
    const int wid  = tid >> 5;
    const int lane = tid & 31;
    const int row0 = blockIdx.x * 64;

    // stage A rows (fp16 direct)
    for (int idx = tid; idx < 1024; idx += 128) {
        int r  = idx >> 4;
        int c8 = (idx & 15) << 3;
        *reinterpret_cast<uint4*>(&As[r * MMS + c8]) =
            *reinterpret_cast<const uint4*>(A + (size_t)(row0 + r) * D + c8);
    }
    // stage B = Wl1^T fp16
    for (int idx = tid; idx < 1024; idx += 128) {
        int n  = idx & 63;
        int k0 = (idx >> 6) << 3;
        __half hv[8];
        #pragma unroll
        for (int j = 0; j < 8; j++) hv[j] = __float2half(__ldg(&Wl1[(k0 + j) * DH + n]));
        *reinterpret_cast<uint4*>(&Bs[n * MMS + k0]) = *reinterpret_cast<uint4*>(hv);
    }
    __syncthreads();

    const uint32_t sbA = smem_u32(As);
    const uint32_t sbB = smem_u32(Bs);
    const int arow = wid * 16 + (((lane >> 3) & 1) << 3) + (lane & 7);
    const int acol = (lane >> 4) << 3;
    uint32_t aaddr = sbA + (uint32_t)(arow * MMS + acol) * 2;
    const int brow = ((lane >> 4) << 3) + (lane & 7);
    const int bcol = lane & 8;
    uint32_t baddr = sbB + (uint32_t)(brow * MMS + bcol) * 2;

    float acc[8][4];
    #pragma unroll
    for (int ni = 0; ni < 8; ni++)
        #pragma unroll
        for (int q = 0; q < 4; q++) acc[ni][q] = 0.f;

    #pragma unroll
    for (int ks = 0; ks < 8; ks++) {
        const uint32_t koff = (uint32_t)ks * 32;
        uint32_t a[4];
        LDSM_X4(a[0], a[1], a[2], a[3], aaddr + koff);
        uint32_t b[8][2];
        #pragma unroll
        for (int g = 0; g < 4; g++) {
            LDSM_X4(b[g * 2][0], b[g * 2][1], b[g * 2 + 1][0], b[g * 2 + 1][1],
                    baddr + koff + (uint32_t)(g * 16 * MMS * 2));
        }
        #pragma unroll
        for (int ni = 0; ni < 8; ni++)
            MMA16816(acc[ni], a, b[ni]);
    }

    __syncthreads();   // done reading As/Bs before overlaying Ts

    // write relu'd t tile to Ts
    const int gid = lane >> 2;
    const int tig = lane & 3;
    #pragma unroll
    for (int half = 0; half < 2; half++) {
        const int r = wid * 16 + half * 8 + gid;
        #pragma unroll
        for (int ni = 0; ni < 8; ni++) {
            const int col = ni * 8 + tig * 2;
            Ts[r * 65 + col]     = fmaxf(acc[ni][half * 2 + 0] + __ldg(&bl1[col]), 0.f);
            Ts[r * 65 + col + 1] = fmaxf(acc[ni][half * 2 + 1] + __ldg(&bl1[col + 1]), 0.f);
        }
    }
    for (int i = tid; i < DH * NCLS; i += 128) W2s[i] = Wl2[i];
    if (tid < NCLS) b2s[tid] = bl2[tid];
    __syncthreads();

    // final 64->10: threads 0..63, one row each
    if (tid < 64) {
        float s[NCLS];
        #pragma unroll
        for (int c = 0; c < NCLS; c++) s[c] = b2s[c];
        #pragma unroll 4
        for (int k = 0; k < DH; k++) {
            float a = Ts[tid * 65 + k];
            #pragma unroll
            for (int c = 0; c < NCLS; c++) s[c] = fmaf(a, W2s[k * NCLS + c], s[c]);
        }
        float* o = out + (size_t)(row0 + tid) * NCLS;
        #pragma unroll
        for (int c = 0; c < NCLS; c++) o[c] = s[c];
    }
}

// ---------------------------------------------------------------------------
// launch
// ---------------------------------------------------------------------------
extern "C" void kernel_launch(void* const* d_in, const int* in_sizes, int n_in,
                              void* d_out, int out_size) {
    const float* h   = (const float*)d_in[0];
    const int*   src = (const int*)  d_in[1];
    const int*   dst = (const int*)  d_in[2];
    const float* W0  = (const float*)d_in[3];
    const float* b0  = (const float*)d_in[4];
    const float* W1  = (const float*)d_in[5];
    const float* b1  = (const float*)d_in[6];
    const float* Wl1 = (const float*)d_in[7];
    const float* bl1 = (const float*)d_in[8];
    const float* Wl2 = (const float*)d_in[9];
    const float* bl2 = (const float*)d_in[10];
    float* out = (float*)d_out;

    void *p_agg, *p_hf;
    cudaGetSymbolAddress(&p_agg, g_agg);
    cudaGetSymbolAddress(&p_hf,  g_hf16);
    __half* agg = (__half*)p_agg;
    __half* hf  = (__half*)p_hf;

    cudaFuncSetAttribute(mma_gemm_kernel,
                         cudaFuncAttributeMaxDynamicSharedMemorySize, MM_SMEM_BYTES);
    cudaFuncSetAttribute(head_kernel,
                         cudaFuncAttributeMaxDynamicSharedMemorySize, HD_SMEM_BYTES);

    const int NB_E = (NEDGES + 255) / 256;
    const int NB_A = (NNODES * 16 + 255) / 256;       // half-warp-per-node grid
    const int NB_M = (NNODES + 127) / 128;            // 313 MMA tiles
    const int NB_H = NNODES / 64;                     // 625 head tiles

    // preprocessing: 3 launches
    hist_conv_kernel<<<NB_E, 256>>>(src, dst, h);
    scan_norms_kernel<<<NPART, SCAN_BLK>>>();
    scatter_kernel<<<NB_E, 256>>>(src, dst);

    // layer 0
    aggregate_kernel<<<NB_A, 256>>>(hf, agg);
    mma_gemm_kernel<<<NB_M, 256, MM_SMEM_BYTES>>>(agg, W0, b0, hf);
    // layer 1
    aggregate_kernel<<<NB_A, 256>>>(hf, agg);
    mma_gemm_kernel<<<NB_M, 256, MM_SMEM_BYTES>>>(agg, W1, b1, hf);
    // fused HMMA MLP head
    head_kernel<<<NB_H, 128, HD_SMEM_BYTES>>>(hf, Wl1, bl1, Wl2, bl2, out);
}

// round 9
// speedup vs baseline: 3.3147x; 1.0739x over previous
#include <cuda_runtime.h>
#include <cuda_fp16.h>
#include <cstdint>
#include <math.h>

// Problem constants
constexpr int NNODES = 40000;
constexpr int NEDGES = 640000;
constexpr int D = 128;
constexpr int DH = 64;
constexpr int NCLS = 10;

constexpr int SCAN_BLK = 512;
constexpr int NPART = (NNODES + SCAN_BLK - 1) / SCAN_BLK;   // 79

// warp-level tensor core ops (arch-agnostic PTX: works on plain sm_100)
#define LDSM_X4(r0, r1, r2, r3, addr)                                          \
    asm volatile("ldmatrix.sync.aligned.m8n8.x4.shared.b16 {%0,%1,%2,%3}, [%4];" \
                 : "=r"(r0), "=r"(r1), "=r"(r2), "=r"(r3) : "r"(addr))

#define MMA16816(c, a, b)                                                       \
    asm volatile("mma.sync.aligned.m16n8k16.row.col.f32.f16.f16.f32 "           \
                 "{%0,%1,%2,%3}, {%4,%5,%6,%7}, {%8,%9}, {%0,%1,%2,%3};"        \
                 : "+f"((c)[0]), "+f"((c)[1]), "+f"((c)[2]), "+f"((c)[3])       \
                 : "r"((a)[0]), "r"((a)[1]), "r"((a)[2]), "r"((a)[3]),          \
                   "r"((b)[0]), "r"((b)[1]))

// single extern shared symbol (one type for the whole TU)
extern __shared__ char smem_raw[];

// ---------------------------------------------------------------------------
// Scratch
// ---------------------------------------------------------------------------
__device__ int    g_cnt_in[NNODES];
__device__ int    g_cnt_out[NNODES];
__device__ float  g_norm_in[NNODES];
__device__ float  g_norm_out[NNODES];
__device__ int    g_row_ptr[NNODES + 1];
__device__ int    g_cursor[NNODES];
__device__ int    g_esrc[NEDGES];               // src node per edge, CSR by dst
__device__ __half g_hf16[(size_t)NNODES * D];   // PRE-SCALED fp16 features
__device__ __half g_agg [(size_t)NNODES * D];   // fp16 aggregation output

__device__ __forceinline__ uint32_t smem_u32(const void* p) {
    uint32_t a;
    asm("{ .reg .u64 t; cvta.to.shared.u64 t, %1; cvt.u32.u64 %0, t; }" : "=r"(a) : "l"(p));
    return a;
}

// ---------------------------------------------------------------------------
// 1. pure degree histogram
// ---------------------------------------------------------------------------
__global__ void hist_kernel(const int* __restrict__ src, const int* __restrict__ dst) {
    int e = blockIdx.x * blockDim.x + threadIdx.x;
    if (e < NEDGES) {
        atomicAdd(&g_cnt_out[src[e]], 1);
        atomicAdd(&g_cnt_in [dst[e]], 1);
    }
}

// ---------------------------------------------------------------------------
// 2. one-kernel scan + norms
// ---------------------------------------------------------------------------
__global__ void scan_norms_kernel() {
    const int base = blockIdx.x * SCAN_BLK;
    const int i    = base + threadIdx.x;
    const int tid  = threadIdx.x, lane = tid & 31, wid = tid >> 5;
    __shared__ int ws[SCAN_BLK / 32];
    __shared__ int s_off;

    int pv = 0;
    for (int j = tid; j < base; j += SCAN_BLK) pv += g_cnt_in[j];
    #pragma unroll
    for (int d = 16; d > 0; d >>= 1) pv += __shfl_xor_sync(0xffffffffu, pv, d);
    if (lane == 0) ws[wid] = pv;
    __syncthreads();
    if (tid == 0) {
        int o = 0;
        #pragma unroll
        for (int w = 0; w < SCAN_BLK / 32; w++) o += ws[w];
        s_off = o;
    }
    __syncthreads();

    int ci = 0;
    if (i < NNODES) {
        ci = g_cnt_in[i];
        int co = g_cnt_out[i];
        g_norm_in [i] = rsqrtf(fmaxf((float)ci, 1.0f));
        g_norm_out[i] = rsqrtf(fmaxf((float)co, 1.0f));
    }
    int incl = ci;
    #pragma unroll
    for (int d = 1; d < 32; d <<= 1) {
        int t = __shfl_up_sync(0xffffffffu, incl, d);
        if (lane >= d) incl += t;
    }
    if (lane == 31) ws[wid] = incl;
    __syncthreads();
    int woff = 0;
    for (int w = 0; w < wid; w++) woff += ws[w];
    int excl = incl - ci + woff + s_off;
    if (i < NNODES) { g_row_ptr[i] = excl; g_cursor[i] = excl; }
    if (i == 0) g_row_ptr[NNODES] = NEDGES;
}

// ---------------------------------------------------------------------------
// 3. scatter edges into CSR + pre-scaled fp16 input conversion
//    (NEDGES == NNODES*D/8, so e also indexes uint4 feature octets)
//    Also re-zeroes counters for the next graph replay.
// ---------------------------------------------------------------------------
__global__ void scatter_conv_kernel(const int* __restrict__ src,
                                    const int* __restrict__ dst,
                                    const float* __restrict__ h) {
    int e = blockIdx.x * blockDim.x + threadIdx.x;
    if (e < NEDGES) {
        int pos = atomicAdd(&g_cursor[dst[e]], 1);
        g_esrc[pos] = src[e];

        // feat[node] = norm_out[node] * h[node]   (node = e/16)
        const float w = __ldg(&g_norm_out[e >> 4]);
        const float4* s4 = reinterpret_cast<const float4*>(h);
        float4 a = __ldg(&s4[e * 2]);
        float4 b = __ldg(&s4[e * 2 + 1]);
        __half2 p0 = __floats2half2_rn(a.x * w, a.y * w);
        __half2 p1 = __floats2half2_rn(a.z * w, a.w * w);
        __half2 p2 = __floats2half2_rn(b.x * w, b.y * w);
        __half2 p3 = __floats2half2_rn(b.z * w, b.w * w);
        uint4 o;
        o.x = *reinterpret_cast<unsigned*>(&p0);
        o.y = *reinterpret_cast<unsigned*>(&p1);
        o.z = *reinterpret_cast<unsigned*>(&p2);
        o.w = *reinterpret_cast<unsigned*>(&p3);
        reinterpret_cast<uint4*>(g_hf16)[e] = o;
    }
    if (e < NNODES) { g_cnt_in[e] = 0; g_cnt_out[e] = 0; }
}

// ---------------------------------------------------------------------------
// 4. aggregation: half-warp per node; features pre-scaled so inner loop is
//    a pure gather-sum. fp16 pairwise tree over 4 edges, fp32 flush.
// ---------------------------------------------------------------------------
__global__ void aggregate_kernel(const __half* __restrict__ hin, __half* __restrict__ aggout) {
    const int gw = (blockIdx.x * blockDim.x + threadIdx.x) >> 4;   // node
    const int sl = threadIdx.x & 15;                               // sublane
    if (gw >= NNODES) return;
    const unsigned hm = (threadIdx.x & 16) ? 0xFFFF0000u : 0x0000FFFFu;
    const int beg = g_row_ptr[gw];
    const int end = g_row_ptr[gw + 1];

    float acc[8] = {0.f, 0.f, 0.f, 0.f, 0.f, 0.f, 0.f, 0.f};
    const uint4* feat = reinterpret_cast<const uint4*>(hin);

    for (int base = beg; base < end; base += 16) {
        const int n = min(16, end - base);
        int my = (base + sl < end) ? __ldg(&g_esrc[base + sl]) : 0;
        int j = 0;
        for (; j + 4 <= n; j += 4) {
            int s0 = __shfl_sync(hm, my, j + 0, 16);
            int s1 = __shfl_sync(hm, my, j + 1, 16);
            int s2 = __shfl_sync(hm, my, j + 2, 16);
            int s3 = __shfl_sync(hm, my, j + 3, 16);
            uint4 q0 = __ldg(feat + (size_t)s0 * 16 + sl);
            uint4 q1 = __ldg(feat + (size_t)s1 * 16 + sl);
            uint4 q2 = __ldg(feat + (size_t)s2 * 16 + sl);
            uint4 q3 = __ldg(feat + (size_t)s3 * 16 + sl);
            const unsigned* u0 = &q0.x;
            const unsigned* u1 = &q1.x;
            const unsigned* u2 = &q2.x;
            const unsigned* u3 = &q3.x;
            #pragma unroll
            for (int r = 0; r < 4; r++) {
                __half2 a01 = __hadd2(*reinterpret_cast<const __half2*>(&u0[r]),
                                      *reinterpret_cast<const __half2*>(&u1[r]));
                __half2 a23 = __hadd2(*reinterpret_cast<const __half2*>(&u2[r]),
                                      *reinterpret_cast<const __half2*>(&u3[r]));
                float2 f = __half22float2(__hadd2(a01, a23));
                acc[2 * r]     += f.x;
                acc[2 * r + 1] += f.y;
            }
        }
        for (; j < n; j++) {
            int s0 = __shfl_sync(hm, my, j, 16);
            uint4 q0 = __ldg(feat + (size_t)s0 * 16 + sl);
            const unsigned* u0 = &q0.x;
            #pragma unroll
            for (int r = 0; r < 4; r++) {
                float2 f = __half22float2(*reinterpret_cast<const __half2*>(&u0[r]));
                acc[2 * r]     += f.x;
                acc[2 * r + 1] += f.y;
            }
        }
    }

    const float win = g_norm_in[gw];
    __half2 p0 = __floats2half2_rn(acc[0] * win, acc[1] * win);
    __half2 p1 = __floats2half2_rn(acc[2] * win, acc[3] * win);
    __half2 p2 = __floats2half2_rn(acc[4] * win, acc[5] * win);
    __half2 p3 = __floats2half2_rn(acc[6] * win, acc[7] * win);
    uint4 o;
    o.x = *reinterpret_cast<unsigned*>(&p0);
    o.y = *reinterpret_cast<unsigned*>(&p1);
    o.z = *reinterpret_cast<unsigned*>(&p2);
    o.w = *reinterpret_cast<unsigned*>(&p3);
    reinterpret_cast<uint4*>(aggout)[(size_t)gw * 16 + sl] = o;
}

// ---------------------------------------------------------------------------
// 5. HMMA GEMM + bias + relu (+ optional norm_out pre-scale of the output):
//    D[128t x 128] = A @ W;  out = (relu(D + b)) * (SCALE_OUT ? norm_out : 1)
// ---------------------------------------------------------------------------
constexpr int MMS = 136;                           // smem row stride in halves (pad)
constexpr int MM_SMEM_BYTES = 2 * 128 * MMS * 2;   // As + Bs = 69632 B

template <bool SCALE_OUT>
__global__ void __launch_bounds__(256)
mma_gemm_kernel(const __half* __restrict__ A,    // [NNODES][128] fp16
                const float* __restrict__ W,     // [128][128] fp32
                const float* __restrict__ bias,  // [128]
                __half* __restrict__ outp) {     // [NNODES][128] fp16
    __half* As = reinterpret_cast<__half*>(smem_raw);      // [128][MMS]
    __half* Bs = As + 128 * MMS;                           // [128][MMS] (Bs[n][k]=W[k][n])

    const int tid  = threadIdx.x;
    const int wid  = tid >> 5;
    const int lane = tid & 31;
    const int row0 = blockIdx.x * 128;

    for (int idx = tid; idx < 2048; idx += 256) {
        int r  = idx >> 4;
        int c8 = (idx & 15) << 3;
        uint4 v = make_uint4(0u, 0u, 0u, 0u);
        if (row0 + r < NNODES)
            v = *reinterpret_cast<const uint4*>(A + (size_t)(row0 + r) * D + c8);
        *reinterpret_cast<uint4*>(&As[r * MMS + c8]) = v;
    }
    for (int idx = tid; idx < 2048; idx += 256) {
        int n  = idx & 127;
        int k0 = (idx >> 7) << 3;
        __half hv[8];
        #pragma unroll
        for (int j = 0; j < 8; j++) hv[j] = __float2half(__ldg(&W[(k0 + j) * D + n]));
        *reinterpret_cast<uint4*>(&Bs[n * MMS + k0]) = *reinterpret_cast<uint4*>(hv);
    }
    __syncthreads();

    const int warpM = wid & 3;
    const int warpN = wid >> 2;

    const uint32_t sbA = smem_u32(As);
    const uint32_t sbB = smem_u32(Bs);
    const int arow = warpM * 32 + (((lane >> 3) & 1) << 3) + (lane & 7);
    const int acol = (lane >> 4) << 3;
    uint32_t aaddr = sbA + (uint32_t)(arow * MMS + acol) * 2;
    const int brow = warpN * 64 + ((lane >> 4) << 3) + (lane & 7);
    const int bcol = lane & 8;
    uint32_t baddr = sbB + (uint32_t)(brow * MMS + bcol) * 2;

    float acc[2][8][4];
    #pragma unroll
    for (int mi = 0; mi < 2; mi++)
        #pragma unroll
        for (int ni = 0; ni < 8; ni++)
            #pragma unroll
            for (int q = 0; q < 4; q++) acc[mi][ni][q] = 0.f;

    #pragma unroll
    for (int ks = 0; ks < 8; ks++) {
        const uint32_t koff = (uint32_t)ks * 32;
        uint32_t a[2][4];
        LDSM_X4(a[0][0], a[0][1], a[0][2], a[0][3], aaddr + koff);
        LDSM_X4(a[1][0], a[1][1], a[1][2], a[1][3], aaddr + koff + (uint32_t)(16 * MMS * 2));
        uint32_t b[8][2];
        #pragma unroll
        for (int g = 0; g < 4; g++) {
            LDSM_X4(b[g * 2][0], b[g * 2][1], b[g * 2 + 1][0], b[g * 2 + 1][1],
                    baddr + koff + (uint32_t)(g * 16 * MMS * 2));
        }
        #pragma unroll
        for (int mi = 0; mi < 2; mi++)
            #pragma unroll
            for (int ni = 0; ni < 8; ni++)
                MMA16816(acc[mi][ni], a[mi], b[ni]);
    }

    const int gid = lane >> 2;
    const int tig = lane & 3;
    #pragma unroll
    for (int mi = 0; mi < 2; mi++) {
        const int r_lo = row0 + warpM * 32 + mi * 16 + gid;
        #pragma unroll
        for (int half = 0; half < 2; half++) {
            const int orow = r_lo + half * 8;
            if (orow >= NNODES) continue;
            float sc = 1.0f;
            if (SCALE_OUT) sc = __ldg(&g_norm_out[orow]);
            #pragma unroll
            for (int ni = 0; ni < 8; ni++) {
                const int col = warpN * 64 + ni * 8 + tig * 2;
                float v0 = fmaxf(acc[mi][ni][half * 2 + 0] + __ldg(&bias[col]), 0.f);
                float v1 = fmaxf(acc[mi][ni][half * 2 + 1] + __ldg(&bias[col + 1]), 0.f);
                if (SCALE_OUT) { v0 *= sc; v1 *= sc; }
                __half2 q = __floats2half2_rn(v0, v1);
                *reinterpret_cast<__half2*>(outp + (size_t)orow * D + col) = q;
            }
        }
    }
}

// ---------------------------------------------------------------------------
// 6. fused HMMA MLP head: t = relu(h2 @ Wl1 + bl1) [64], out = t @ Wl2 + bl2
// ---------------------------------------------------------------------------
constexpr int HD_SMEM_BYTES = 2 * 64 * MMS * 2;   // As + Bs = 34816 B

__global__ void __launch_bounds__(128)
head_kernel(const __half* __restrict__ A,     // h2 [NNODES][128] fp16
            const float* __restrict__ Wl1,    // [128][64]
            const float* __restrict__ bl1,    // [64]
            const float* __restrict__ Wl2,    // [64][10]
            const float* __restrict__ bl2,    // [10]
            float* __restrict__ out) {        // [NNODES][10]
    __half* As = reinterpret_cast<__half*>(smem_raw);   // [64][MMS]
    __half* Bs = As + 64 * MMS;                         // [64][MMS]
    float* Ts  = reinterpret_cast<float*>(smem_raw);    // [64][65] (phase 2)
    float* W2s = Ts + 64 * 65;
    float* b2s = W2s + DH * NCLS;

    const int tid  = threadIdx.x;
    const int wid  = tid >> 5;
    const int lane = tid & 31;
    const int row0 = blockIdx.x * 64;

    for (int idx = tid; idx < 1024; idx += 128) {
        int r  = idx >> 4;
        int c8 = (idx & 15) << 3;
        *reinterpret_cast<uint4*>(&As[r * MMS + c8]) =
            *reinterpret_cast<const uint4*>(A + (size_t)(row0 + r) * D + c8);
    }
    for (int idx = tid; idx < 1024; idx += 128) {
        int n  = idx & 63;
        int k0 = (idx >> 6) << 3;
        __half hv[8];
        #pragma unroll
        for (int j = 0; j < 8; j++) hv[j] = __float2half(__ldg(&Wl1[(k0 + j) * DH + n]));
        *reinterpret_cast<uint4*>(&Bs[n * MMS + k0]) = *reinterpret_cast<uint4*>(hv);
    }
    __syncthreads();

    const uint32_t sbA = smem_u32(As);
    const uint32_t sbB = smem_u32(Bs);
    const int arow = wid * 16 + (((lane >> 3) & 1) << 3) + (lane & 7);
    const int acol = (lane >> 4) << 3;
    uint32_t aaddr = sbA + (uint32_t)(arow * MMS + acol) * 2;
    const int brow = ((lane >> 4) << 3) + (lane & 7);
    const int bcol = lane & 8;
    uint32_t baddr = sbB + (uint32_t)(brow * MMS + bcol) * 2;

    float acc[8][4];
    #pragma unroll
    for (int ni = 0; ni < 8; ni++)
        #pragma unroll
        for (int q = 0; q < 4; q++) acc[ni][q] = 0.f;

    #pragma unroll
    for (int ks = 0; ks < 8; ks++) {
        const uint32_t koff = (uint32_t)ks * 32;
        uint32_t a[4];
        LDSM_X4(a[0], a[1], a[2], a[3], aaddr + koff);
        uint32_t b[8][2];
        #pragma unroll
        for (int g = 0; g < 4; g++) {
            LDSM_X4(b[g * 2][0], b[g * 2][1], b[g * 2 + 1][0], b[g * 2 + 1][1],
                    baddr + koff + (uint32_t)(g * 16 * MMS * 2));
        }
        #pragma unroll
        for (int ni = 0; ni < 8; ni++)
            MMA16816(acc[ni], a, b[ni]);
    }

    __syncthreads();

    const int gid = lane >> 2;
    const int tig = lane & 3;
    #pragma unroll
    for (int half = 0; half < 2; half++) {
        const int r = wid * 16 + half * 8 + gid;
        #pragma unroll
        for (int ni = 0; ni < 8; ni++) {
            const int col = ni * 8 + tig * 2;
            Ts[r * 65 + col]     = fmaxf(acc[ni][half * 2 + 0] + __ldg(&bl1[col]), 0.f);
            Ts[r * 65 + col + 1] = fmaxf(acc[ni][half * 2 + 1] + __ldg(&bl1[col + 1]), 0.f);
        }
    }
    for (int i = tid; i < DH * NCLS; i += 128) W2s[i] = Wl2[i];
    if (tid < NCLS) b2s[tid] = bl2[tid];
    __syncthreads();

    if (tid < 64) {
        float s[NCLS];
        #pragma unroll
        for (int c = 0; c < NCLS; c++) s[c] = b2s[c];
        #pragma unroll 4
        for (int k = 0; k < DH; k++) {
            float a = Ts[tid * 65 + k];
            #pragma unroll
            for (int c = 0; c < NCLS; c++) s[c] = fmaf(a, W2s[k * NCLS + c], s[c]);
        }
        float* o = out + (size_t)(row0 + tid) * NCLS;
        #pragma unroll
        for (int c = 0; c < NCLS; c++) o[c] = s[c];
    }
}

// ---------------------------------------------------------------------------
// launch
// ---------------------------------------------------------------------------
extern "C" void kernel_launch(void* const* d_in, const int* in_sizes, int n_in,
                              void* d_out, int out_size) {
    const float* h   = (const float*)d_in[0];
    const int*   src = (const int*)  d_in[1];
    const int*   dst = (const int*)  d_in[2];
    const float* W0  = (const float*)d_in[3];
    const float* b0  = (const float*)d_in[4];
    const float* W1  = (const float*)d_in[5];
    const float* b1  = (const float*)d_in[6];
    const float* Wl1 = (const float*)d_in[7];
    const float* bl1 = (const float*)d_in[8];
    const float* Wl2 = (const float*)d_in[9];
    const float* bl2 = (const float*)d_in[10];
    float* out = (float*)d_out;

    void *p_agg, *p_hf;
    cudaGetSymbolAddress(&p_agg, g_agg);
    cudaGetSymbolAddress(&p_hf,  g_hf16);
    __half* agg = (__half*)p_agg;
    __half* hf  = (__half*)p_hf;

    cudaFuncSetAttribute(mma_gemm_kernel<true>,
                         cudaFuncAttributeMaxDynamicSharedMemorySize, MM_SMEM_BYTES);
    cudaFuncSetAttribute(mma_gemm_kernel<false>,
                         cudaFuncAttributeMaxDynamicSharedMemorySize, MM_SMEM_BYTES);
    cudaFuncSetAttribute(head_kernel,
                         cudaFuncAttributeMaxDynamicSharedMemorySize, HD_SMEM_BYTES);

    const int NB_E = (NEDGES + 255) / 256;
    const int NB_A = (NNODES * 16 + 255) / 256;       // half-warp-per-node grid
    const int NB_M = (NNODES + 127) / 128;            // 313 MMA tiles
    const int NB_H = NNODES / 64;                     // 625 head tiles

    // preprocessing: 3 launches
    hist_kernel<<<NB_E, 256>>>(src, dst);
    scan_norms_kernel<<<NPART, SCAN_BLK>>>();
    scatter_conv_kernel<<<NB_E, 256>>>(src, dst, h);

    // layer 0 (GEMM writes h1 pre-scaled by norm_out for the next aggregation)
    aggregate_kernel<<<NB_A, 256>>>(hf, agg);
    mma_gemm_kernel<true><<<NB_M, 256, MM_SMEM_BYTES>>>(agg, W0, b0, hf);
    // layer 1 (plain output; feeds the head)
    aggregate_kernel<<<NB_A, 256>>>(hf, agg);
    mma_gemm_kernel<false><<<NB_M, 256, MM_SMEM_BYTES>>>(agg, W1, b1, hf);
    // fused HMMA MLP head
    head_kernel<<<NB_H, 128, HD_SMEM_BYTES>>>(hf, Wl1, bl1, Wl2, bl2, out);
}